// round 7
// baseline (speedup 1.0000x reference)
#include <cuda_runtime.h>
#include <cuda_bf16.h>
#include <mma.h>
#include <cstdint>

using namespace nvcuda;

#define NN    10000
#define EE    320000
#define ET    330000    // EE + NN self loops
#define GG    100
#define CHN   250       // HEADS*OUT
#define HOUT  125
#define SLOPE 0.2f

#define MT    128       // GEMM M tile
#define NT    256       // padded N
#define MPAD  10112     // 79 * 128
#define KP1   384       // K=336 padded
#define KP2   256       // K=250 padded
#define BK    32

// ---------------- scratch (static device globals; no allocation) -------------
__device__ float g_h[NN * CHN];
__device__ float g_fa[NN * CHN];
__device__ float g_fb[NN * CHN];
__device__ float g_esrc[NN * 2];
__device__ float g_edst[NN * 2];
__device__ int   g_cnt[NN];
__device__ int   g_off[NN + 1];
__device__ int   g_pos[NN];
__device__ int   g_csr[ET];
__device__ float g_pool[GG * CHN];
__device__ float g_l1[GG * 200];
__device__ float g_l2[GG * 100];
__device__ float g_l3[GG * 100];
__device__ __align__(256) __nv_bfloat16 g_ahi[MPAD * KP1];
__device__ __align__(256) __nv_bfloat16 g_alo[MPAD * KP1];
__device__ __align__(256) __nv_bfloat16 g_whi[NT * KP1];
__device__ __align__(256) __nv_bfloat16 g_wlo[NT * KP1];

// ---------------- helpers ------------------------------------------------------
__device__ __forceinline__ uint32_t smem_u32(const void* p) {
    uint32_t a;
    asm("{ .reg .u64 t; cvta.to.shared.u64 t, %1; cvt.u32.u64 %0, t; }" : "=r"(a) : "l"(p));
    return a;
}
__device__ __forceinline__ void cp_async16(uint32_t dst, const void* src) {
    asm volatile("cp.async.cg.shared.global [%0], [%1], 16;" :: "r"(dst), "l"(src));
}
__device__ __forceinline__ void cp_commit() {
    asm volatile("cp.async.commit_group;" ::: "memory");
}
__device__ __forceinline__ void cp_wait0() {
    asm volatile("cp.async.wait_group 0;" ::: "memory");
}
__device__ __forceinline__ void cp_wait1() {
    asm volatile("cp.async.wait_group 1;" ::: "memory");
}

// ---------------- CSR build --------------------------------------------------
__global__ void zero_cnt_kernel() {
    int i = blockIdx.x * blockDim.x + threadIdx.x;
    if (i < NN) g_cnt[i] = 0;
}
__global__ void count_kernel(const int* __restrict__ ei) {
    int i = blockIdx.x * blockDim.x + threadIdx.x;
    if (i >= ET) return;
    int dst = (i < EE) ? ei[EE + i] : (i - EE);
    atomicAdd(&g_cnt[dst], 1);
}
__global__ void scan_kernel() {
    __shared__ int sp[1024];
    int t = threadIdx.x;
    int base = t * 10;
    int loc[10];
    int sum = 0;
#pragma unroll
    for (int i = 0; i < 10; i++) {
        int idx = base + i;
        int v = (idx < NN) ? g_cnt[idx] : 0;
        loc[i] = sum; sum += v;
    }
    sp[t] = sum;
    __syncthreads();
    for (int off = 1; off < 1024; off <<= 1) {
        int v = (t >= off) ? sp[t - off] : 0;
        __syncthreads();
        sp[t] += v;
        __syncthreads();
    }
    int pre = sp[t] - sum;
#pragma unroll
    for (int i = 0; i < 10; i++) {
        int idx = base + i;
        if (idx < NN) g_off[idx] = pre + loc[i];
    }
    if (t == 1023) g_off[NN] = sp[1023];
}
__global__ void init_pos_kernel() {
    int i = blockIdx.x * blockDim.x + threadIdx.x;
    if (i < NN) g_pos[i] = g_off[i];
}
__global__ void scatter_kernel(const int* __restrict__ ei) {
    int i = blockIdx.x * blockDim.x + threadIdx.x;
    if (i >= ET) return;
    int src, dst;
    if (i < EE) { src = ei[i]; dst = ei[EE + i]; }
    else        { src = i - EE; dst = i - EE; }
    int p = atomicAdd(&g_pos[dst], 1);
    g_csr[p] = src;
}

// ---------------- fp32 -> bf16 hi/lo split ------------------------------------
__global__ void split_a_kernel(const float* __restrict__ in, int K, int Kpad) {
    int idx = blockIdx.x * blockDim.x + threadIdx.x;
    if (idx >= MPAD * Kpad) return;
    int r = idx / Kpad, k = idx - r * Kpad;
    float v = (r < NN && k < K) ? in[(size_t)r * K + k] : 0.f;
    __nv_bfloat16 h = __float2bfloat16(v);
    __nv_bfloat16 l = __float2bfloat16(v - __bfloat162float(h));
    g_ahi[idx] = h; g_alo[idx] = l;
}
__global__ void split_w_kernel(const float* __restrict__ W, int K, int Kpad) {
    int idx = blockIdx.x * blockDim.x + threadIdx.x;
    if (idx >= NT * Kpad) return;
    int n = idx / Kpad, k = idx - n * Kpad;
    float v = (n < CHN && k < K) ? W[(size_t)k * CHN + n] : 0.f;
    __nv_bfloat16 h = __float2bfloat16(v);
    __nv_bfloat16 l = __float2bfloat16(v - __bfloat162float(h));
    g_whi[idx] = h; g_wlo[idx] = l;
}

// ---------------- WMMA bf16 GEMM (hi/lo split via K-concatenation) ------------
// C = Ahi*Bhi + Ahi*Blo + Alo*Bhi  folded as K' = 3*Kpad segments.
// Block tile 128x128, 8 warps (4m x 2n), warp tile 32x64, BK=32, cp.async 2-stage.
#define ALD  40    // A smem row lead (bf16 elems)
#define BLD  40
#define CLD  136   // C smem row lead (f32 elems)
#define A_ST (128 * ALD)             // elems per A stage
#define B_ST (128 * BLD)

__global__ __launch_bounds__(256) void gemm_wmma_kernel(
    const __nv_bfloat16* __restrict__ Ahi, const __nv_bfloat16* __restrict__ Alo,
    const __nv_bfloat16* __restrict__ Bhi, const __nv_bfloat16* __restrict__ Blo,
    int Kpad, float* __restrict__ hout)
{
    extern __shared__ char smem[];
    __nv_bfloat16* As = (__nv_bfloat16*)smem;                  // [2][128][ALD]
    __nv_bfloat16* Bs = (__nv_bfloat16*)smem + 2 * A_ST;       // [2][128][BLD]
    float* Cs = (float*)smem;                                   // [128][CLD] (reuse)

    int tid = threadIdx.x;
    int wid = tid >> 5;
    int wm = wid >> 1;          // 0..3  warp row
    int wn = wid & 1;           // 0..1  warp col
    int m0 = blockIdx.x * MT;
    int n0 = blockIdx.y * 128;

    uint32_t asmem = smem_u32(As);
    uint32_t bsmem = smem_u32(Bs);

    int row = tid >> 2;          // 0..63 (x2 iters covers 128)
    int grp = tid & 3;           // 16B chunk within 32-elem row

    int niter = (3 * Kpad) >> 5;  // K' / 32

    // -------- load one stage via cp.async --------
    auto load_stage = [&](int st, int kb) {
        int kp = kb << 5;                   // global k'
        int seg = kp / Kpad;
        int kk = kp - seg * Kpad;
        const __nv_bfloat16* aseg = (seg < 2) ? Ahi : Alo;
        const __nv_bfloat16* bseg = (seg == 1) ? Blo : Bhi;
#pragma unroll
        for (int i = 0; i < 2; i++) {
            int r = row + i * 64;
            uint32_t d = asmem + (st * A_ST + r * ALD + grp * 8) * 2;
            cp_async16(d, aseg + (size_t)(m0 + r) * Kpad + kk + grp * 8);
        }
#pragma unroll
        for (int i = 0; i < 2; i++) {
            int r = row + i * 64;
            uint32_t d = bsmem + (st * B_ST + r * BLD + grp * 8) * 2;
            cp_async16(d, bseg + (size_t)(n0 + r) * Kpad + kk + grp * 8);
        }
        cp_commit();
    };

    wmma::fragment<wmma::accumulator, 16, 16, 16, float> c[2][4];
#pragma unroll
    for (int i = 0; i < 2; i++)
#pragma unroll
        for (int j = 0; j < 4; j++) wmma::fill_fragment(c[i][j], 0.f);

    load_stage(0, 0);
    for (int kb = 0; kb < niter; kb++) {
        int st = kb & 1;
        if (kb + 1 < niter) { load_stage(st ^ 1, kb + 1); cp_wait1(); }
        else                { cp_wait0(); }
        __syncthreads();

        const __nv_bfloat16* at = As + st * A_ST + wm * 32 * ALD;
        const __nv_bfloat16* bt = Bs + st * B_ST + wn * 64 * BLD;
#pragma unroll
        for (int ks = 0; ks < 2; ks++) {
            wmma::fragment<wmma::matrix_a, 16, 16, 16, __nv_bfloat16, wmma::row_major> a0, a1;
            wmma::load_matrix_sync(a0, at + ks * 16, ALD);
            wmma::load_matrix_sync(a1, at + 16 * ALD + ks * 16, ALD);
#pragma unroll
            for (int j = 0; j < 4; j++) {
                wmma::fragment<wmma::matrix_b, 16, 16, 16, __nv_bfloat16, wmma::col_major> b;
                wmma::load_matrix_sync(b, bt + j * 16 * BLD + ks * 16, BLD);
                wmma::mma_sync(c[0][j], a0, b, c[0][j]);
                wmma::mma_sync(c[1][j], a1, b, c[1][j]);
            }
        }
        __syncthreads();
    }

    // -------- epilogue: c frags -> smem -> coalesced global store --------
#pragma unroll
    for (int i = 0; i < 2; i++)
#pragma unroll
        for (int j = 0; j < 4; j++)
            wmma::store_matrix_sync(Cs + (wm * 32 + i * 16) * CLD + wn * 64 + j * 16,
                                    c[i][j], CLD, wmma::mem_row_major);
    __syncthreads();

#pragma unroll
    for (int it = 0; it < 64; it++) {
        int idx = it * 256 + tid;
        int r = idx >> 7, cc = idx & 127;
        int grow = m0 + r, gcol = n0 + cc;
        if (grow < NN && gcol < CHN)
            hout[(size_t)grow * CHN + gcol] = Cs[r * CLD + cc];
    }
}

// ---------------- attention dot products per node ----------------------------
__global__ void att_kernel(const float* __restrict__ asrc,
                           const float* __restrict__ adst)
{
    int warp = threadIdx.x >> 5;
    int lane = threadIdx.x & 31;
    int n = blockIdx.x * 4 + warp;
    if (n >= NN) return;
    float s0s = 0.f, s1s = 0.f, s0d = 0.f, s1d = 0.f;
    const float* hr = g_h + (size_t)n * CHN;
    for (int c = lane; c < CHN; c += 32) {
        float v = hr[c];
        float as = asrc[c], ad = adst[c];
        if (c < HOUT) { s0s += v * as; s0d += v * ad; }
        else          { s1s += v * as; s1d += v * ad; }
    }
#pragma unroll
    for (int o = 16; o; o >>= 1) {
        s0s += __shfl_xor_sync(0xffffffffu, s0s, o);
        s1s += __shfl_xor_sync(0xffffffffu, s1s, o);
        s0d += __shfl_xor_sync(0xffffffffu, s0d, o);
        s1d += __shfl_xor_sync(0xffffffffu, s1d, o);
    }
    if (lane == 0) {
        g_esrc[2 * n + 0] = s0s;
        g_esrc[2 * n + 1] = s1s;
        g_edst[2 * n + 0] = s0d;
        g_edst[2 * n + 1] = s1d;
    }
}

__device__ __forceinline__ float leaky(float x) { return x > 0.f ? x : SLOPE * x; }

// ---------------- aggregation: one block per destination node ----------------
__global__ __launch_bounds__(128) void agg_kernel(const float* __restrict__ bias,
                                                  float* __restrict__ out)
{
    int i = blockIdx.x;
    int tid = threadIdx.x;
    int lane = tid & 31, warp = tid >> 5;

    __shared__ float w0[4], w1[4];
    __shared__ int   s_src[128];
    __shared__ float s_a0[128], s_a1[128];

    int s = g_off[i], e = g_off[i + 1];
    float ed0 = g_edst[2 * i], ed1 = g_edst[2 * i + 1];

    float m0 = -1e30f, m1 = -1e30f;
    for (int j = s + tid; j < e; j += 128) {
        int src = g_csr[j];
        float a0 = leaky(g_esrc[2 * src] + ed0);
        float a1 = leaky(g_esrc[2 * src + 1] + ed1);
        m0 = fmaxf(m0, a0); m1 = fmaxf(m1, a1);
    }
#pragma unroll
    for (int o = 16; o; o >>= 1) {
        m0 = fmaxf(m0, __shfl_xor_sync(0xffffffffu, m0, o));
        m1 = fmaxf(m1, __shfl_xor_sync(0xffffffffu, m1, o));
    }
    if (lane == 0) { w0[warp] = m0; w1[warp] = m1; }
    __syncthreads();
    m0 = fmaxf(fmaxf(w0[0], w0[1]), fmaxf(w0[2], w0[3]));
    m1 = fmaxf(fmaxf(w1[0], w1[1]), fmaxf(w1[2], w1[3]));
    __syncthreads();

    float d0 = 0.f, d1 = 0.f;
    for (int j = s + tid; j < e; j += 128) {
        int src = g_csr[j];
        float a0 = leaky(g_esrc[2 * src] + ed0);
        float a1 = leaky(g_esrc[2 * src + 1] + ed1);
        d0 += __expf(a0 - m0);
        d1 += __expf(a1 - m1);
    }
#pragma unroll
    for (int o = 16; o; o >>= 1) {
        d0 += __shfl_xor_sync(0xffffffffu, d0, o);
        d1 += __shfl_xor_sync(0xffffffffu, d1, o);
    }
    if (lane == 0) { w0[warp] = d0; w1[warp] = d1; }
    __syncthreads();
    d0 = w0[0] + w0[1] + w0[2] + w0[3] + 1e-16f;
    d1 = w1[0] + w1[1] + w1[2] + w1[3] + 1e-16f;
    float r0 = 1.0f / d0, r1 = 1.0f / d1;

    float acc0 = 0.f, acc1 = 0.f;
    int c0 = 2 * tid;
    bool act = (tid < HOUT);
    bool head0a = (c0 < HOUT);
    bool head0b = (c0 + 1 < HOUT);

    for (int base = s; base < e; base += 128) {
        int j = base + tid;
        if (j < e) {
            int src = g_csr[j];
            float a0 = leaky(g_esrc[2 * src] + ed0);
            float a1 = leaky(g_esrc[2 * src + 1] + ed1);
            s_src[tid] = src;
            s_a0[tid] = __expf(a0 - m0) * r0;
            s_a1[tid] = __expf(a1 - m1) * r1;
        }
        __syncthreads();
        int cnt = min(128, e - base);
        if (act) {
#pragma unroll 4
            for (int k = 0; k < cnt; k++) {
                int src = s_src[k];
                float2 hv = *(const float2*)(g_h + (size_t)src * CHN + c0);
                float aa = head0a ? s_a0[k] : s_a1[k];
                float ab = head0b ? s_a0[k] : s_a1[k];
                acc0 += aa * hv.x;
                acc1 += ab * hv.y;
            }
        }
        __syncthreads();
    }
    if (act) {
        float v0 = acc0 + bias[c0];
        float v1 = acc1 + bias[c0 + 1];
        out[(size_t)i * CHN + c0]     = v0 > 0.f ? v0 : 0.f;
        out[(size_t)i * CHN + c0 + 1] = v1 > 0.f ? v1 : 0.f;
    }
}

// ---------------- global mean pool -------------------------------------------
__global__ void pool_kernel(const int* __restrict__ batch,
                            const float* __restrict__ feat)
{
    int g = blockIdx.x;
    __shared__ int ss, se;
    if (threadIdx.x == 0) {
        int lo = 0, hi = NN;
        while (lo < hi) { int mid = (lo + hi) >> 1; if (batch[mid] < g) lo = mid + 1; else hi = mid; }
        ss = lo;
        lo = 0; hi = NN;
        while (lo < hi) { int mid = (lo + hi) >> 1; if (batch[mid] < g + 1) lo = mid + 1; else hi = mid; }
        se = lo;
    }
    __syncthreads();
    int c = threadIdx.x;
    if (c < CHN) {
        float sum = 0.f;
        for (int i = ss; i < se; i++) sum += feat[(size_t)i * CHN + c];
        float cntf = (float)(se - ss);
        g_pool[g * CHN + c] = sum / fmaxf(cntf, 1.0f);
    }
}

// ---------------- tiny linear layers -----------------------------------------
__global__ void lin_kernel(const float* __restrict__ in, const float* __restrict__ w,
                           const float* __restrict__ b, float* __restrict__ out,
                           int Gr, int K, int Dout, int relu)
{
    int idx = blockIdx.x * blockDim.x + threadIdx.x;
    if (idx >= Gr * Dout) return;
    int g = idx / Dout, j = idx % Dout;
    float s = b[j];
    for (int k = 0; k < K; k++) s += in[g * K + k] * w[k * Dout + j];
    if (relu) s = fmaxf(s, 0.f);
    out[idx] = s;
}

// ---------------- driver ------------------------------------------------------
#define GEMM_SMEM (128 * CLD * 4)   // 69632 (C reuse >= tile region 40960)

extern "C" void kernel_launch(void* const* d_in, const int* in_sizes, int n_in,
                              void* d_out, int out_size)
{
    const float* x     = (const float*)d_in[0];
    const int*   ei    = (const int*)d_in[1];
    const int*   batch = (const int*)d_in[2];
    const float* W[4]    = {(const float*)d_in[3],  (const float*)d_in[7],
                            (const float*)d_in[11], (const float*)d_in[15]};
    const float* Asrc[4] = {(const float*)d_in[4],  (const float*)d_in[8],
                            (const float*)d_in[12], (const float*)d_in[16]};
    const float* Adst[4] = {(const float*)d_in[5],  (const float*)d_in[9],
                            (const float*)d_in[13], (const float*)d_in[17]};
    const float* Bb[4]   = {(const float*)d_in[6],  (const float*)d_in[10],
                            (const float*)d_in[14], (const float*)d_in[18]};
    const float* lw1 = (const float*)d_in[19]; const float* lb1 = (const float*)d_in[20];
    const float* lw2 = (const float*)d_in[21]; const float* lb2 = (const float*)d_in[22];
    const float* lw3 = (const float*)d_in[23]; const float* lb3 = (const float*)d_in[24];
    const float* lw4 = (const float*)d_in[25]; const float* lb4 = (const float*)d_in[26];
    float* out = (float*)d_out;

    float *hP, *faP, *fbP, *poolP, *l1P, *l2P, *l3P;
    __nv_bfloat16 *ahiP, *aloP, *whiP, *wloP;
    cudaGetSymbolAddress((void**)&hP,    g_h);
    cudaGetSymbolAddress((void**)&faP,   g_fa);
    cudaGetSymbolAddress((void**)&fbP,   g_fb);
    cudaGetSymbolAddress((void**)&poolP, g_pool);
    cudaGetSymbolAddress((void**)&l1P,   g_l1);
    cudaGetSymbolAddress((void**)&l2P,   g_l2);
    cudaGetSymbolAddress((void**)&l3P,   g_l3);
    cudaGetSymbolAddress((void**)&ahiP,  g_ahi);
    cudaGetSymbolAddress((void**)&aloP,  g_alo);
    cudaGetSymbolAddress((void**)&whiP,  g_whi);
    cudaGetSymbolAddress((void**)&wloP,  g_wlo);

    cudaFuncSetAttribute(gemm_wmma_kernel,
                         cudaFuncAttributeMaxDynamicSharedMemorySize, GEMM_SMEM);

    // CSR build
    zero_cnt_kernel<<<(NN + 255) / 256, 256>>>();
    count_kernel<<<(ET + 255) / 256, 256>>>(ei);
    scan_kernel<<<1, 1024>>>();
    init_pos_kernel<<<(NN + 255) / 256, 256>>>();
    scatter_kernel<<<(ET + 255) / 256, 256>>>(ei);

    const float* fin = x;
    float* fouts[4] = {faP, fbP, faP, fbP};
    int Ks[4]    = {336, 250, 250, 250};
    int Kpads[4] = {KP1, KP2, KP2, KP2};

    dim3 ggrid(MPAD / MT, 2);
    for (int l = 0; l < 4; l++) {
        int K = Ks[l], Kpad = Kpads[l];
        split_a_kernel<<<(MPAD * Kpad + 255) / 256, 256>>>(fin, K, Kpad);
        split_w_kernel<<<(NT * Kpad + 255) / 256, 256>>>(W[l], K, Kpad);
        gemm_wmma_kernel<<<ggrid, 256, GEMM_SMEM>>>(ahiP, aloP, whiP, wloP, Kpad, hP);
        att_kernel<<<(NN + 3) / 4, 128>>>(Asrc[l], Adst[l]);
        agg_kernel<<<NN, 128>>>(Bb[l], fouts[l]);
        fin = fouts[l];
    }

    pool_kernel<<<GG, 256>>>(batch, fouts[3]);

    lin_kernel<<<(GG * 200 + 127) / 128, 128>>>(poolP, lw1, lb1, l1P, GG, 250, 200, 1);
    lin_kernel<<<(GG * 100 + 127) / 128, 128>>>(l1P,   lw2, lb2, l2P, GG, 200, 100, 1);
    lin_kernel<<<(GG * 100 + 127) / 128, 128>>>(l2P,   lw3, lb3, l3P, GG, 100, 100, 1);
    lin_kernel<<<(GG * 29  + 127) / 128, 128>>>(l3P,   lw4, lb4, out, GG, 100, 29,  0);
}

// round 8
// speedup vs baseline: 1.1439x; 1.1439x over previous
#include <cuda_runtime.h>
#include <cuda_bf16.h>
#include <mma.h>
#include <cstdint>

using namespace nvcuda;

#define NN    10000
#define EE    320000
#define ET    330000
#define GG    100
#define CHN   250
#define HOUT  125
#define SLOPE 0.2f

#define MT    128
#define NT    256
#define MPAD  10112     // 79 * 128
#define KP1   384       // layer1 K=336 padded
#define KP2   256       // layers 2-4 K=250 padded

// ---------------- scratch ------------------------------------------------------
__device__ float  g_h[NN * CHN];             // GEMM output fp32 (gather source)
__device__ float  g_fa[NN * CHN];            // layer-4 output fp32 (pool source)
__device__ float4 g_att0[NN];                // es0, ed0, es1a, ed1a  (tile by=0)
__device__ float2 g_att1[NN];                // es1b, ed1b            (tile by=1)
__device__ int    g_cnt[NN];
__device__ int    g_off[NN + 1];
__device__ int    g_pos[NN];
__device__ int    g_csr[ET];
__device__ __align__(256) __nv_bfloat16 g_ahi[MPAD * KP1];   // layer1 A hi
__device__ __align__(256) __nv_bfloat16 g_alo[MPAD * KP1];   // layer1 A lo
__device__ __align__(256) __nv_bfloat16 g_ahi2[MPAD * KP2];  // layers2-4 A hi (agg-written)
__device__ __align__(256) __nv_bfloat16 g_alo2[MPAD * KP2];
// weights: layer0 at 0 (NT*KP1), layer l>=1 at NT*KP1 + (l-1)*NT*KP2
#define WOFF1 (NT * KP1)
__device__ __align__(256) __nv_bfloat16 g_whi[NT * KP1 + 3 * NT * KP2];
__device__ __align__(256) __nv_bfloat16 g_wlo[NT * KP1 + 3 * NT * KP2];

// ---------------- helpers ------------------------------------------------------
__device__ __forceinline__ uint32_t smem_u32(const void* p) {
    uint32_t a;
    asm("{ .reg .u64 t; cvta.to.shared.u64 t, %1; cvt.u32.u64 %0, t; }" : "=r"(a) : "l"(p));
    return a;
}
__device__ __forceinline__ void cp_async16(uint32_t dst, const void* src) {
    asm volatile("cp.async.cg.shared.global [%0], [%1], 16;" :: "r"(dst), "l"(src));
}
__device__ __forceinline__ void cp_commit() { asm volatile("cp.async.commit_group;" ::: "memory"); }
__device__ __forceinline__ void cp_wait0()  { asm volatile("cp.async.wait_group 0;" ::: "memory"); }
__device__ __forceinline__ void cp_wait1()  { asm volatile("cp.async.wait_group 1;" ::: "memory"); }
__device__ __forceinline__ float leaky(float x) { return x > 0.f ? x : SLOPE * x; }

// ---------------- init: zero counts + zero pad rows of ahi2/alo2 ---------------
__global__ void init_kernel() {
    int i = blockIdx.x * blockDim.x + threadIdx.x;
    if (i < NN) g_cnt[i] = 0;
    // pad rows 10000..10111 (stride KP2): 112*256 = 28672 elems per array
    int p = i - NN;
    if (p >= 0 && p < 112 * KP2) {
        int idx = 10000 * KP2 + p;
        g_ahi2[idx] = __float2bfloat16(0.f);
        g_alo2[idx] = __float2bfloat16(0.f);
    }
}
__global__ void count_kernel(const int* __restrict__ ei) {
    int i = blockIdx.x * blockDim.x + threadIdx.x;
    if (i >= ET) return;
    int dst = (i < EE) ? ei[EE + i] : (i - EE);
    atomicAdd(&g_cnt[dst], 1);
}
__global__ void scan_kernel() {
    __shared__ int sp[1024];
    int t = threadIdx.x;
    int base = t * 10;
    int loc[10];
    int sum = 0;
#pragma unroll
    for (int i = 0; i < 10; i++) {
        int idx = base + i;
        int v = (idx < NN) ? g_cnt[idx] : 0;
        loc[i] = sum; sum += v;
    }
    sp[t] = sum;
    __syncthreads();
    for (int off = 1; off < 1024; off <<= 1) {
        int v = (t >= off) ? sp[t - off] : 0;
        __syncthreads();
        sp[t] += v;
        __syncthreads();
    }
    int pre = sp[t] - sum;
#pragma unroll
    for (int i = 0; i < 10; i++) {
        int idx = base + i;
        if (idx < NN) { int o = pre + loc[i]; g_off[idx] = o; g_pos[idx] = o; }
    }
    if (t == 1023) g_off[NN] = sp[1023];
}
__global__ void scatter_kernel(const int* __restrict__ ei) {
    int i = blockIdx.x * blockDim.x + threadIdx.x;
    if (i >= ET) return;
    int src, dst;
    if (i < EE) { src = ei[i]; dst = ei[EE + i]; }
    else        { src = i - EE; dst = i - EE; }
    int p = atomicAdd(&g_pos[dst], 1);
    g_csr[p] = src;
}

// ---------------- splits -------------------------------------------------------
__global__ void split_a_kernel(const float* __restrict__ in) {
    int idx = blockIdx.x * blockDim.x + threadIdx.x;
    if (idx >= MPAD * KP1) return;
    int r = idx / KP1, k = idx - r * KP1;
    float v = (r < NN && k < 336) ? in[(size_t)r * 336 + k] : 0.f;
    __nv_bfloat16 h = __float2bfloat16(v);
    __nv_bfloat16 l = __float2bfloat16(v - __bfloat162float(h));
    g_ahi[idx] = h; g_alo[idx] = l;
}
// all four weight matrices in one pass
__global__ void split_w_all_kernel(const float* __restrict__ W1, const float* __restrict__ W2,
                                   const float* __restrict__ W3, const float* __restrict__ W4)
{
    int idx = blockIdx.x * blockDim.x + threadIdx.x;
    int total = NT * KP1 + 3 * NT * KP2;
    if (idx >= total) return;
    const float* W; int K, Kpad, rem;
    if (idx < NT * KP1) { W = W1; K = 336; Kpad = KP1; rem = idx; }
    else {
        int idx2 = idx - NT * KP1;
        int l = idx2 / (NT * KP2);
        rem = idx2 - l * (NT * KP2);
        W = (l == 0) ? W2 : (l == 1) ? W3 : W4;
        K = 250; Kpad = KP2;
    }
    int n = rem / Kpad, k = rem - n * Kpad;
    float v = (n < CHN && k < K) ? W[(size_t)k * CHN + n] : 0.f;
    __nv_bfloat16 h = __float2bfloat16(v);
    __nv_bfloat16 l = __float2bfloat16(v - __bfloat162float(h));
    g_whi[idx] = h; g_wlo[idx] = l;
}

// ---------------- WMMA GEMM + fused attention dots -----------------------------
#define ALD  40
#define BLD  40
#define CLD  136
#define A_ST (128 * ALD)
#define B_ST (128 * BLD)
#define GEMM_SMEM (128 * CLD * 4)

__global__ __launch_bounds__(256) void gemm_wmma_kernel(
    const __nv_bfloat16* __restrict__ Ahi, const __nv_bfloat16* __restrict__ Alo,
    const __nv_bfloat16* __restrict__ Bhi, const __nv_bfloat16* __restrict__ Blo,
    int Kpad,
    const float* __restrict__ asrc, const float* __restrict__ adst,
    float* __restrict__ hout)
{
    extern __shared__ char smem[];
    __nv_bfloat16* As = (__nv_bfloat16*)smem;
    __nv_bfloat16* Bs = (__nv_bfloat16*)smem + 2 * A_ST;
    float* Cs = (float*)smem;
    __shared__ float s_as[128], s_ad[128];

    int tid = threadIdx.x;
    int wid = tid >> 5;
    int wm = wid >> 1, wn = wid & 1;
    int m0 = blockIdx.x * MT;
    int by = blockIdx.y;
    int n0 = by * 128;

    if (tid < 128) {
        int col = n0 + tid;
        s_as[tid] = (col < CHN) ? asrc[col] : 0.f;
        s_ad[tid] = (col < CHN) ? adst[col] : 0.f;
    }

    uint32_t asmem = smem_u32(As);
    uint32_t bsmem = smem_u32(Bs);
    int row = tid >> 2;
    int grp = tid & 3;
    int niter = (3 * Kpad) >> 5;

    auto load_stage = [&](int st, int kb) {
        int kp = kb << 5;
        int seg = kp / Kpad;
        int kk = kp - seg * Kpad;
        const __nv_bfloat16* aseg = (seg < 2) ? Ahi : Alo;
        const __nv_bfloat16* bseg = (seg == 1) ? Blo : Bhi;
#pragma unroll
        for (int i = 0; i < 2; i++) {
            int r = row + i * 64;
            uint32_t d = asmem + (st * A_ST + r * ALD + grp * 8) * 2;
            cp_async16(d, aseg + (size_t)(m0 + r) * Kpad + kk + grp * 8);
        }
#pragma unroll
        for (int i = 0; i < 2; i++) {
            int r = row + i * 64;
            uint32_t d = bsmem + (st * B_ST + r * BLD + grp * 8) * 2;
            cp_async16(d, bseg + (size_t)(n0 + r) * Kpad + kk + grp * 8);
        }
        cp_commit();
    };

    wmma::fragment<wmma::accumulator, 16, 16, 16, float> c[2][4];
#pragma unroll
    for (int i = 0; i < 2; i++)
#pragma unroll
        for (int j = 0; j < 4; j++) wmma::fill_fragment(c[i][j], 0.f);

    load_stage(0, 0);
    for (int kb = 0; kb < niter; kb++) {
        int st = kb & 1;
        if (kb + 1 < niter) { load_stage(st ^ 1, kb + 1); cp_wait1(); }
        else                { cp_wait0(); }
        __syncthreads();

        const __nv_bfloat16* at = As + st * A_ST + wm * 32 * ALD;
        const __nv_bfloat16* bt = Bs + st * B_ST + wn * 64 * BLD;
#pragma unroll
        for (int ks = 0; ks < 2; ks++) {
            wmma::fragment<wmma::matrix_a, 16, 16, 16, __nv_bfloat16, wmma::row_major> a0, a1;
            wmma::load_matrix_sync(a0, at + ks * 16, ALD);
            wmma::load_matrix_sync(a1, at + 16 * ALD + ks * 16, ALD);
#pragma unroll
            for (int j = 0; j < 4; j++) {
                wmma::fragment<wmma::matrix_b, 16, 16, 16, __nv_bfloat16, wmma::col_major> b;
                wmma::load_matrix_sync(b, bt + j * 16 * BLD + ks * 16, BLD);
                wmma::mma_sync(c[0][j], a0, b, c[0][j]);
                wmma::mma_sync(c[1][j], a1, b, c[1][j]);
            }
        }
        __syncthreads();
    }

    // epilogue: frags -> Cs
#pragma unroll
    for (int i = 0; i < 2; i++)
#pragma unroll
        for (int j = 0; j < 4; j++)
            wmma::store_matrix_sync(Cs + (wm * 32 + i * 16) * CLD + wn * 64 + j * 16,
                                    c[i][j], CLD, wmma::mem_row_major);
    __syncthreads();

    // coalesced store of h
#pragma unroll
    for (int it = 0; it < 64; it++) {
        int idx = it * 256 + tid;
        int r = idx >> 7, cc = idx & 127;
        int grow = m0 + r, gcol = n0 + cc;
        if (grow < NN && gcol < CHN)
            hout[(size_t)grow * CHN + gcol] = Cs[r * CLD + cc];
    }

    // fused attention dots: 2 threads per row, 64 cols each
    {
        int r = tid >> 1;
        int half = tid & 1;
        int ccb = half * 64;
        float s0 = 0.f, d0 = 0.f, s1 = 0.f, d1 = 0.f;
#pragma unroll 8
        for (int q = 0; q < 64; q++) {
            int cc = ccb + q;
            float v = Cs[r * CLD + cc];
            float a = s_as[cc], bvd = s_ad[cc];
            if (n0 + cc < HOUT) { s0 += v * a; d0 += v * bvd; }
            else                { s1 += v * a; d1 += v * bvd; }
        }
        s0 += __shfl_xor_sync(0xffffffffu, s0, 1);
        d0 += __shfl_xor_sync(0xffffffffu, d0, 1);
        s1 += __shfl_xor_sync(0xffffffffu, s1, 1);
        d1 += __shfl_xor_sync(0xffffffffu, d1, 1);
        int grow = m0 + r;
        if (half == 0 && grow < NN) {
            if (by == 0) g_att0[grow] = make_float4(s0, d0, s1, d1);
            else         g_att1[grow] = make_float2(s1, d1);
        }
    }
}

// ---------------- aggregation (softmax + gather), bf16 hi/lo or fp32 out -------
__global__ __launch_bounds__(128) void agg_kernel(const float* __restrict__ bias,
                                                  __nv_bfloat16* __restrict__ ohi,
                                                  __nv_bfloat16* __restrict__ olo,
                                                  float* __restrict__ of32,
                                                  int f32out)
{
    int i = blockIdx.x;
    int tid = threadIdx.x;
    int lane = tid & 31, warp = tid >> 5;

    __shared__ float w0[4], w1[4];
    __shared__ int   s_src[128];
    __shared__ float s_a0[128], s_a1[128];

    int s = g_off[i], e = g_off[i + 1];
    float4 a0i = g_att0[i];
    float2 a1i = g_att1[i];
    float ed0 = a0i.y, ed1 = a0i.w + a1i.y;

    float m0 = -1e30f, m1 = -1e30f;
    for (int j = s + tid; j < e; j += 128) {
        int src = g_csr[j];
        float4 b0 = g_att0[src]; float2 b1 = g_att1[src];
        float v0 = leaky(b0.x + ed0);
        float v1 = leaky(b0.z + b1.x + ed1);
        m0 = fmaxf(m0, v0); m1 = fmaxf(m1, v1);
    }
#pragma unroll
    for (int o = 16; o; o >>= 1) {
        m0 = fmaxf(m0, __shfl_xor_sync(0xffffffffu, m0, o));
        m1 = fmaxf(m1, __shfl_xor_sync(0xffffffffu, m1, o));
    }
    if (lane == 0) { w0[warp] = m0; w1[warp] = m1; }
    __syncthreads();
    m0 = fmaxf(fmaxf(w0[0], w0[1]), fmaxf(w0[2], w0[3]));
    m1 = fmaxf(fmaxf(w1[0], w1[1]), fmaxf(w1[2], w1[3]));
    __syncthreads();

    float d0 = 0.f, d1 = 0.f;
    for (int j = s + tid; j < e; j += 128) {
        int src = g_csr[j];
        float4 b0 = g_att0[src]; float2 b1 = g_att1[src];
        d0 += __expf(leaky(b0.x + ed0) - m0);
        d1 += __expf(leaky(b0.z + b1.x + ed1) - m1);
    }
#pragma unroll
    for (int o = 16; o; o >>= 1) {
        d0 += __shfl_xor_sync(0xffffffffu, d0, o);
        d1 += __shfl_xor_sync(0xffffffffu, d1, o);
    }
    if (lane == 0) { w0[warp] = d0; w1[warp] = d1; }
    __syncthreads();
    d0 = w0[0] + w0[1] + w0[2] + w0[3] + 1e-16f;
    d1 = w1[0] + w1[1] + w1[2] + w1[3] + 1e-16f;
    float r0 = 1.0f / d0, r1 = 1.0f / d1;

    float acc0 = 0.f, acc1 = 0.f;
    int c0 = 2 * tid;
    bool act = (tid < HOUT);
    bool head0a = (c0 < HOUT);
    bool head0b = (c0 + 1 < HOUT);

    for (int base = s; base < e; base += 128) {
        int j = base + tid;
        if (j < e) {
            int src = g_csr[j];
            float4 b0 = g_att0[src]; float2 b1 = g_att1[src];
            s_src[tid] = src;
            s_a0[tid] = __expf(leaky(b0.x + ed0) - m0) * r0;
            s_a1[tid] = __expf(leaky(b0.z + b1.x + ed1) - m1) * r1;
        }
        __syncthreads();
        int cnt = min(128, e - base);
        if (act) {
#pragma unroll 4
            for (int k = 0; k < cnt; k++) {
                int src = s_src[k];
                float2 hv = *(const float2*)(g_h + (size_t)src * CHN + c0);
                float aa = head0a ? s_a0[k] : s_a1[k];
                float ab = head0b ? s_a0[k] : s_a1[k];
                acc0 += aa * hv.x;
                acc1 += ab * hv.y;
            }
        }
        __syncthreads();
    }

    if (f32out) {
        if (act) {
            float v0 = fmaxf(acc0 + bias[c0], 0.f);
            float v1 = fmaxf(acc1 + bias[c0 + 1], 0.f);
            of32[(size_t)i * CHN + c0]     = v0;
            of32[(size_t)i * CHN + c0 + 1] = v1;
        }
    } else {
        // write bf16 hi/lo into stride-KP2 A buffer for next GEMM
        size_t o = (size_t)i * KP2 + c0;
        if (act) {
            float v0 = fmaxf(acc0 + bias[c0], 0.f);
            float v1 = fmaxf(acc1 + bias[c0 + 1], 0.f);
            __nv_bfloat16 h0 = __float2bfloat16(v0);
            __nv_bfloat16 h1 = __float2bfloat16(v1);
            __nv_bfloat16 l0 = __float2bfloat16(v0 - __bfloat162float(h0));
            __nv_bfloat16 l1 = __float2bfloat16(v1 - __bfloat162float(h1));
            *(__nv_bfloat162*)(ohi + o) = __nv_bfloat162(h0, h1);
            *(__nv_bfloat162*)(olo + o) = __nv_bfloat162(l0, l1);
        } else {
            // zero K-padding cols 250..255
            __nv_bfloat162 z(__float2bfloat16(0.f), __float2bfloat16(0.f));
            *(__nv_bfloat162*)(ohi + o) = z;
            *(__nv_bfloat162*)(olo + o) = z;
        }
    }
}

// ---------------- fused pool + 4-layer MLP (one block per graph) ---------------
__global__ __launch_bounds__(256) void pool_mlp_kernel(
    const int* __restrict__ batch, const float* __restrict__ feat,
    const float* __restrict__ lw1, const float* __restrict__ lb1,
    const float* __restrict__ lw2, const float* __restrict__ lb2,
    const float* __restrict__ lw3, const float* __restrict__ lb3,
    const float* __restrict__ lw4, const float* __restrict__ lb4,
    float* __restrict__ out)
{
    int g = blockIdx.x;
    int tid = threadIdx.x;
    __shared__ int ss, se;
    __shared__ float sg[CHN], t1[200], t2[100], t3[100];

    if (tid == 0) {
        int lo = 0, hi = NN;
        while (lo < hi) { int mid = (lo + hi) >> 1; if (batch[mid] < g) lo = mid + 1; else hi = mid; }
        ss = lo;
        lo = 0; hi = NN;
        while (lo < hi) { int mid = (lo + hi) >> 1; if (batch[mid] < g + 1) lo = mid + 1; else hi = mid; }
        se = lo;
    }
    __syncthreads();
    if (tid < CHN) {
        float sum = 0.f;
        for (int i = ss; i < se; i++) sum += feat[(size_t)i * CHN + tid];
        sg[tid] = sum / fmaxf((float)(se - ss), 1.0f);
    }
    __syncthreads();
    if (tid < 200) {
        float s = lb1[tid];
        for (int k = 0; k < 250; k++) s += sg[k] * lw1[k * 200 + tid];
        t1[tid] = fmaxf(s, 0.f);
    }
    __syncthreads();
    if (tid < 100) {
        float s = lb2[tid];
        for (int k = 0; k < 200; k++) s += t1[k] * lw2[k * 100 + tid];
        t2[tid] = fmaxf(s, 0.f);
    }
    __syncthreads();
    if (tid < 100) {
        float s = lb3[tid];
        for (int k = 0; k < 100; k++) s += t2[k] * lw3[k * 100 + tid];
        t3[tid] = fmaxf(s, 0.f);
    }
    __syncthreads();
    if (tid < 29) {
        float s = lb4[tid];
        for (int k = 0; k < 100; k++) s += t3[k] * lw4[k * 29 + tid];
        out[g * 29 + tid] = s;
    }
}

// ---------------- driver --------------------------------------------------------
extern "C" void kernel_launch(void* const* d_in, const int* in_sizes, int n_in,
                              void* d_out, int out_size)
{
    const float* x     = (const float*)d_in[0];
    const int*   ei    = (const int*)d_in[1];
    const int*   batch = (const int*)d_in[2];
    const float* W[4]    = {(const float*)d_in[3],  (const float*)d_in[7],
                            (const float*)d_in[11], (const float*)d_in[15]};
    const float* Asrc[4] = {(const float*)d_in[4],  (const float*)d_in[8],
                            (const float*)d_in[12], (const float*)d_in[16]};
    const float* Adst[4] = {(const float*)d_in[5],  (const float*)d_in[9],
                            (const float*)d_in[13], (const float*)d_in[17]};
    const float* Bb[4]   = {(const float*)d_in[6],  (const float*)d_in[10],
                            (const float*)d_in[14], (const float*)d_in[18]};
    const float* lw1 = (const float*)d_in[19]; const float* lb1 = (const float*)d_in[20];
    const float* lw2 = (const float*)d_in[21]; const float* lb2 = (const float*)d_in[22];
    const float* lw3 = (const float*)d_in[23]; const float* lb3 = (const float*)d_in[24];
    const float* lw4 = (const float*)d_in[25]; const float* lb4 = (const float*)d_in[26];
    float* out = (float*)d_out;

    float *hP, *faP;
    __nv_bfloat16 *ahiP, *aloP, *ahi2P, *alo2P, *whiP, *wloP;
    cudaGetSymbolAddress((void**)&hP,    g_h);
    cudaGetSymbolAddress((void**)&faP,   g_fa);
    cudaGetSymbolAddress((void**)&ahiP,  g_ahi);
    cudaGetSymbolAddress((void**)&aloP,  g_alo);
    cudaGetSymbolAddress((void**)&ahi2P, g_ahi2);
    cudaGetSymbolAddress((void**)&alo2P, g_alo2);
    cudaGetSymbolAddress((void**)&whiP,  g_whi);
    cudaGetSymbolAddress((void**)&wloP,  g_wlo);

    cudaFuncSetAttribute(gemm_wmma_kernel,
                         cudaFuncAttributeMaxDynamicSharedMemorySize, GEMM_SMEM);

    // CSR + init (4 launches)
    init_kernel<<<(NN + 112 * KP2 + 255) / 256, 256>>>();
    count_kernel<<<(ET + 255) / 256, 256>>>(ei);
    scan_kernel<<<1, 1024>>>();
    scatter_kernel<<<(ET + 255) / 256, 256>>>(ei);

    // splits (2 launches)
    split_a_kernel<<<(MPAD * KP1 + 255) / 256, 256>>>(x);
    int wtotal = NT * KP1 + 3 * NT * KP2;
    split_w_all_kernel<<<(wtotal + 255) / 256, 256>>>(W[0], W[1], W[2], W[3]);

    dim3 ggrid(MPAD / MT, 2);
    for (int l = 0; l < 4; l++) {
        const __nv_bfloat16* Ah = (l == 0) ? ahiP : ahi2P;
        const __nv_bfloat16* Al = (l == 0) ? aloP : alo2P;
        int Kpad = (l == 0) ? KP1 : KP2;
        size_t woff = (l == 0) ? 0 : (size_t)WOFF1 + (size_t)(l - 1) * NT * KP2;
        gemm_wmma_kernel<<<ggrid, 256, GEMM_SMEM>>>(
            Ah, Al, whiP + woff, wloP + woff, Kpad, Asrc[l], Adst[l], hP);
        agg_kernel<<<NN, 128>>>(Bb[l], ahi2P, alo2P, faP, (l == 3) ? 1 : 0);
    }

    pool_mlp_kernel<<<GG, 256>>>(batch, faP, lw1, lb1, lw2, lb2, lw3, lb3, lw4, lb4, out);
}

// round 9
// speedup vs baseline: 1.2504x; 1.0931x over previous
#include <cuda_runtime.h>
#include <cuda_bf16.h>
#include <cuda_fp16.h>
#include <mma.h>
#include <cstdint>

using namespace nvcuda;

#define NN    10000
#define EE    320000
#define ET    330000
#define GG    100
#define CHN   250
#define HOUT  125
#define SLOPE 0.2f

#define MT    128
#define NT    256
#define MPAD  10112     // 79 * 128
#define KP1   384       // layer1 K=336 padded
#define KP2   256       // layers 2-4 K=250 padded

// ---------------- scratch ------------------------------------------------------
__device__ __half g_hh[MPAD * 256];          // GEMM output fp16 (gather source), stride 256
__device__ float  g_fa[NN * CHN];            // layer-4 output fp32 (pool source)
__device__ float4 g_att0[NN];                // es0, ed0, es1a, ed1a  (tile by=0)
__device__ float2 g_att1[NN];                // es1b, ed1b            (tile by=1)
__device__ int    g_cnt[NN];
__device__ int    g_off[NN + 1];
__device__ int    g_pos[NN];
__device__ int    g_csr[ET];
__device__ __align__(256) __nv_bfloat16 g_ahi[MPAD * KP1];   // layer1 A hi
__device__ __align__(256) __nv_bfloat16 g_alo[MPAD * KP1];   // layer1 A lo
__device__ __align__(256) __nv_bfloat16 g_ahi2[MPAD * KP2];  // layers2-4 A hi (agg-written)
__device__ __align__(256) __nv_bfloat16 g_alo2[MPAD * KP2];
#define WOFF1 (NT * KP1)
__device__ __align__(256) __nv_bfloat16 g_whi[NT * KP1 + 3 * NT * KP2];
__device__ __align__(256) __nv_bfloat16 g_wlo[NT * KP1 + 3 * NT * KP2];

// ---------------- helpers ------------------------------------------------------
__device__ __forceinline__ uint32_t smem_u32(const void* p) {
    uint32_t a;
    asm("{ .reg .u64 t; cvta.to.shared.u64 t, %1; cvt.u32.u64 %0, t; }" : "=r"(a) : "l"(p));
    return a;
}
__device__ __forceinline__ void cp_async16(uint32_t dst, const void* src) {
    asm volatile("cp.async.cg.shared.global [%0], [%1], 16;" :: "r"(dst), "l"(src));
}
__device__ __forceinline__ void cp_commit() { asm volatile("cp.async.commit_group;" ::: "memory"); }
__device__ __forceinline__ void cp_wait0()  { asm volatile("cp.async.wait_group 0;" ::: "memory"); }
__device__ __forceinline__ void cp_wait1()  { asm volatile("cp.async.wait_group 1;" ::: "memory"); }
__device__ __forceinline__ float leaky(float x) { return x > 0.f ? x : SLOPE * x; }

// ---------------- init: zero counts + zero pad rows of ahi2/alo2 ---------------
__global__ void init_kernel() {
    int i = blockIdx.x * blockDim.x + threadIdx.x;
    if (i < NN) g_cnt[i] = 0;
    int p = i - NN;
    if (p >= 0 && p < 112 * KP2) {
        int idx = 10000 * KP2 + p;
        g_ahi2[idx] = __float2bfloat16(0.f);
        g_alo2[idx] = __float2bfloat16(0.f);
    }
}
__global__ void count_kernel(const int* __restrict__ ei) {
    int i = blockIdx.x * blockDim.x + threadIdx.x;
    if (i >= ET) return;
    int dst = (i < EE) ? ei[EE + i] : (i - EE);
    atomicAdd(&g_cnt[dst], 1);
}
__global__ void scan_kernel() {
    __shared__ int sp[1024];
    int t = threadIdx.x;
    int base = t * 10;
    int loc[10];
    int sum = 0;
#pragma unroll
    for (int i = 0; i < 10; i++) {
        int idx = base + i;
        int v = (idx < NN) ? g_cnt[idx] : 0;
        loc[i] = sum; sum += v;
    }
    sp[t] = sum;
    __syncthreads();
    for (int off = 1; off < 1024; off <<= 1) {
        int v = (t >= off) ? sp[t - off] : 0;
        __syncthreads();
        sp[t] += v;
        __syncthreads();
    }
    int pre = sp[t] - sum;
#pragma unroll
    for (int i = 0; i < 10; i++) {
        int idx = base + i;
        if (idx < NN) { int o = pre + loc[i]; g_off[idx] = o; g_pos[idx] = o; }
    }
    if (t == 1023) g_off[NN] = sp[1023];
}
__global__ void scatter_kernel(const int* __restrict__ ei) {
    int i = blockIdx.x * blockDim.x + threadIdx.x;
    if (i >= ET) return;
    int src, dst;
    if (i < EE) { src = ei[i]; dst = ei[EE + i]; }
    else        { src = i - EE; dst = i - EE; }
    int p = atomicAdd(&g_pos[dst], 1);
    g_csr[p] = src;
}

// ---------------- splits -------------------------------------------------------
__global__ void split_a_kernel(const float* __restrict__ in) {
    int idx = blockIdx.x * blockDim.x + threadIdx.x;
    if (idx >= MPAD * KP1) return;
    int r = idx / KP1, k = idx - r * KP1;
    float v = (r < NN && k < 336) ? in[(size_t)r * 336 + k] : 0.f;
    __nv_bfloat16 h = __float2bfloat16(v);
    __nv_bfloat16 l = __float2bfloat16(v - __bfloat162float(h));
    g_ahi[idx] = h; g_alo[idx] = l;
}
__global__ void split_w_all_kernel(const float* __restrict__ W1, const float* __restrict__ W2,
                                   const float* __restrict__ W3, const float* __restrict__ W4)
{
    int idx = blockIdx.x * blockDim.x + threadIdx.x;
    int total = NT * KP1 + 3 * NT * KP2;
    if (idx >= total) return;
    const float* W; int K, Kpad, rem;
    if (idx < NT * KP1) { W = W1; K = 336; Kpad = KP1; rem = idx; }
    else {
        int idx2 = idx - NT * KP1;
        int l = idx2 / (NT * KP2);
        rem = idx2 - l * (NT * KP2);
        W = (l == 0) ? W2 : (l == 1) ? W3 : W4;
        K = 250; Kpad = KP2;
    }
    int n = rem / Kpad, k = rem - n * Kpad;
    float v = (n < CHN && k < K) ? W[(size_t)k * CHN + n] : 0.f;
    __nv_bfloat16 h = __float2bfloat16(v);
    __nv_bfloat16 l = __float2bfloat16(v - __bfloat162float(h));
    g_whi[idx] = h; g_wlo[idx] = l;
}

// ---------------- WMMA GEMM + fused attention dots + fp16 h store --------------
#define ALD  40
#define BLD  40
#define CLD  136
#define A_ST (128 * ALD)
#define B_ST (128 * BLD)
#define GEMM_SMEM (128 * CLD * 4)

__global__ __launch_bounds__(256) void gemm_wmma_kernel(
    const __nv_bfloat16* __restrict__ Ahi, const __nv_bfloat16* __restrict__ Alo,
    const __nv_bfloat16* __restrict__ Bhi, const __nv_bfloat16* __restrict__ Blo,
    int Kpad,
    const float* __restrict__ asrc, const float* __restrict__ adst,
    __half* __restrict__ hout)
{
    extern __shared__ char smem[];
    __nv_bfloat16* As = (__nv_bfloat16*)smem;
    __nv_bfloat16* Bs = (__nv_bfloat16*)smem + 2 * A_ST;
    float* Cs = (float*)smem;
    __shared__ float s_as[128], s_ad[128];

    int tid = threadIdx.x;
    int wid = tid >> 5;
    int wm = wid >> 1, wn = wid & 1;
    int m0 = blockIdx.x * MT;
    int by = blockIdx.y;
    int n0 = by * 128;

    if (tid < 128) {
        int col = n0 + tid;
        s_as[tid] = (col < CHN) ? asrc[col] : 0.f;
        s_ad[tid] = (col < CHN) ? adst[col] : 0.f;
    }

    uint32_t asmem = smem_u32(As);
    uint32_t bsmem = smem_u32(Bs);
    int row = tid >> 2;
    int grp = tid & 3;
    int niter = (3 * Kpad) >> 5;

    auto load_stage = [&](int st, int kb) {
        int kp = kb << 5;
        int seg = kp / Kpad;
        int kk = kp - seg * Kpad;
        const __nv_bfloat16* aseg = (seg < 2) ? Ahi : Alo;
        const __nv_bfloat16* bseg = (seg == 1) ? Blo : Bhi;
#pragma unroll
        for (int i = 0; i < 2; i++) {
            int r = row + i * 64;
            uint32_t d = asmem + (st * A_ST + r * ALD + grp * 8) * 2;
            cp_async16(d, aseg + (size_t)(m0 + r) * Kpad + kk + grp * 8);
        }
#pragma unroll
        for (int i = 0; i < 2; i++) {
            int r = row + i * 64;
            uint32_t d = bsmem + (st * B_ST + r * BLD + grp * 8) * 2;
            cp_async16(d, bseg + (size_t)(n0 + r) * Kpad + kk + grp * 8);
        }
        cp_commit();
    };

    wmma::fragment<wmma::accumulator, 16, 16, 16, float> c[2][4];
#pragma unroll
    for (int i = 0; i < 2; i++)
#pragma unroll
        for (int j = 0; j < 4; j++) wmma::fill_fragment(c[i][j], 0.f);

    load_stage(0, 0);
    for (int kb = 0; kb < niter; kb++) {
        int st = kb & 1;
        if (kb + 1 < niter) { load_stage(st ^ 1, kb + 1); cp_wait1(); }
        else                { cp_wait0(); }
        __syncthreads();

        const __nv_bfloat16* at = As + st * A_ST + wm * 32 * ALD;
        const __nv_bfloat16* bt = Bs + st * B_ST + wn * 64 * BLD;
#pragma unroll
        for (int ks = 0; ks < 2; ks++) {
            wmma::fragment<wmma::matrix_a, 16, 16, 16, __nv_bfloat16, wmma::row_major> a0, a1;
            wmma::load_matrix_sync(a0, at + ks * 16, ALD);
            wmma::load_matrix_sync(a1, at + 16 * ALD + ks * 16, ALD);
#pragma unroll
            for (int j = 0; j < 4; j++) {
                wmma::fragment<wmma::matrix_b, 16, 16, 16, __nv_bfloat16, wmma::col_major> b;
                wmma::load_matrix_sync(b, bt + j * 16 * BLD + ks * 16, BLD);
                wmma::mma_sync(c[0][j], a0, b, c[0][j]);
                wmma::mma_sync(c[1][j], a1, b, c[1][j]);
            }
        }
        __syncthreads();
    }

    // epilogue: frags -> Cs
#pragma unroll
    for (int i = 0; i < 2; i++)
#pragma unroll
        for (int j = 0; j < 4; j++)
            wmma::store_matrix_sync(Cs + (wm * 32 + i * 16) * CLD + wn * 64 + j * 16,
                                    c[i][j], CLD, wmma::mem_row_major);
    __syncthreads();

    // coalesced fp16 store of h (stride 256; gather never reads cols >= 250)
#pragma unroll
    for (int it = 0; it < 32; it++) {
        int idx = it * 256 + tid;          // 8192 half2 slots
        int r = idx >> 6, c2 = idx & 63;
        int grow = m0 + r, gcol = n0 + 2 * c2;
        if (grow < NN && gcol < CHN) {
            float v0 = Cs[r * CLD + 2 * c2];
            float v1 = Cs[r * CLD + 2 * c2 + 1];
            *(__half2*)(hout + (size_t)grow * 256 + gcol) = __floats2half2_rn(v0, v1);
        }
    }

    // fused attention dots: 2 threads per row, 64 cols each
    {
        int r = tid >> 1;
        int half = tid & 1;
        int ccb = half * 64;
        float s0 = 0.f, d0 = 0.f, s1 = 0.f, d1 = 0.f;
#pragma unroll 8
        for (int q = 0; q < 64; q++) {
            int cc = ccb + q;
            float v = Cs[r * CLD + cc];
            float a = s_as[cc], bvd = s_ad[cc];
            if (n0 + cc < HOUT) { s0 += v * a; d0 += v * bvd; }
            else                { s1 += v * a; d1 += v * bvd; }
        }
        s0 += __shfl_xor_sync(0xffffffffu, s0, 1);
        d0 += __shfl_xor_sync(0xffffffffu, d0, 1);
        s1 += __shfl_xor_sync(0xffffffffu, s1, 1);
        d1 += __shfl_xor_sync(0xffffffffu, d1, 1);
        int grow = m0 + r;
        if (half == 0 && grow < NN) {
            if (by == 0) g_att0[grow] = make_float4(s0, d0, s1, d1);
            else         g_att1[grow] = make_float2(s1, d1);
        }
    }
}

// ---------------- aggregation (softmax + fp16 gather) ---------------------------
__global__ __launch_bounds__(128) void agg_kernel(const float* __restrict__ bias,
                                                  __nv_bfloat16* __restrict__ ohi,
                                                  __nv_bfloat16* __restrict__ olo,
                                                  float* __restrict__ of32,
                                                  int f32out)
{
    int i = blockIdx.x;
    int tid = threadIdx.x;
    int lane = tid & 31, warp = tid >> 5;

    __shared__ float w0[4], w1[4];
    __shared__ int   s_src[128];
    __shared__ float s_a0[128], s_a1[128];

    int s = g_off[i], e = g_off[i + 1];
    float4 a0i = g_att0[i];
    float2 a1i = g_att1[i];
    float ed0 = a0i.y, ed1 = a0i.w + a1i.y;

    float m0 = -1e30f, m1 = -1e30f;
    for (int j = s + tid; j < e; j += 128) {
        int src = g_csr[j];
        float4 b0 = g_att0[src]; float2 b1 = g_att1[src];
        float v0 = leaky(b0.x + ed0);
        float v1 = leaky(b0.z + b1.x + ed1);
        m0 = fmaxf(m0, v0); m1 = fmaxf(m1, v1);
    }
#pragma unroll
    for (int o = 16; o; o >>= 1) {
        m0 = fmaxf(m0, __shfl_xor_sync(0xffffffffu, m0, o));
        m1 = fmaxf(m1, __shfl_xor_sync(0xffffffffu, m1, o));
    }
    if (lane == 0) { w0[warp] = m0; w1[warp] = m1; }
    __syncthreads();
    m0 = fmaxf(fmaxf(w0[0], w0[1]), fmaxf(w0[2], w0[3]));
    m1 = fmaxf(fmaxf(w1[0], w1[1]), fmaxf(w1[2], w1[3]));
    __syncthreads();

    float d0 = 0.f, d1 = 0.f;
    for (int j = s + tid; j < e; j += 128) {
        int src = g_csr[j];
        float4 b0 = g_att0[src]; float2 b1 = g_att1[src];
        d0 += __expf(leaky(b0.x + ed0) - m0);
        d1 += __expf(leaky(b0.z + b1.x + ed1) - m1);
    }
#pragma unroll
    for (int o = 16; o; o >>= 1) {
        d0 += __shfl_xor_sync(0xffffffffu, d0, o);
        d1 += __shfl_xor_sync(0xffffffffu, d1, o);
    }
    if (lane == 0) { w0[warp] = d0; w1[warp] = d1; }
    __syncthreads();
    d0 = w0[0] + w0[1] + w0[2] + w0[3] + 1e-16f;
    d1 = w1[0] + w1[1] + w1[2] + w1[3] + 1e-16f;
    float r0 = 1.0f / d0, r1 = 1.0f / d1;

    float acc0 = 0.f, acc1 = 0.f;
    int c0 = 2 * tid;
    bool act = (tid < HOUT);
    bool head0a = (c0 < HOUT);
    bool head0b = (c0 + 1 < HOUT);

    for (int base = s; base < e; base += 128) {
        int j = base + tid;
        if (j < e) {
            int src = g_csr[j];
            float4 b0 = g_att0[src]; float2 b1 = g_att1[src];
            s_src[tid] = src;
            s_a0[tid] = __expf(leaky(b0.x + ed0) - m0) * r0;
            s_a1[tid] = __expf(leaky(b0.z + b1.x + ed1) - m1) * r1;
        }
        __syncthreads();
        int cnt = min(128, e - base);
        if (act) {
#pragma unroll 4
            for (int k = 0; k < cnt; k++) {
                int src = s_src[k];
                __half2 hv2 = *(const __half2*)(g_hh + (size_t)src * 256 + c0);
                float2 hv = __half22float2(hv2);
                float aa = head0a ? s_a0[k] : s_a1[k];
                float ab = head0b ? s_a0[k] : s_a1[k];
                acc0 += aa * hv.x;
                acc1 += ab * hv.y;
            }
        }
        __syncthreads();
    }

    if (f32out) {
        if (act) {
            float v0 = fmaxf(acc0 + bias[c0], 0.f);
            float v1 = fmaxf(acc1 + bias[c0 + 1], 0.f);
            of32[(size_t)i * CHN + c0]     = v0;
            of32[(size_t)i * CHN + c0 + 1] = v1;
        }
    } else {
        size_t o = (size_t)i * KP2 + c0;
        if (act) {
            float v0 = fmaxf(acc0 + bias[c0], 0.f);
            float v1 = fmaxf(acc1 + bias[c0 + 1], 0.f);
            __nv_bfloat16 h0 = __float2bfloat16(v0);
            __nv_bfloat16 h1 = __float2bfloat16(v1);
            __nv_bfloat16 l0 = __float2bfloat16(v0 - __bfloat162float(h0));
            __nv_bfloat16 l1 = __float2bfloat16(v1 - __bfloat162float(h1));
            *(__nv_bfloat162*)(ohi + o) = __nv_bfloat162(h0, h1);
            *(__nv_bfloat162*)(olo + o) = __nv_bfloat162(l0, l1);
        } else {
            __nv_bfloat162 z(__float2bfloat16(0.f), __float2bfloat16(0.f));
            *(__nv_bfloat162*)(ohi + o) = z;
            *(__nv_bfloat162*)(olo + o) = z;
        }
    }
}

// ---------------- fused pool + 4-layer MLP (one block per graph) ---------------
__global__ __launch_bounds__(256) void pool_mlp_kernel(
    const int* __restrict__ batch, const float* __restrict__ feat,
    const float* __restrict__ lw1, const float* __restrict__ lb1,
    const float* __restrict__ lw2, const float* __restrict__ lb2,
    const float* __restrict__ lw3, const float* __restrict__ lb3,
    const float* __restrict__ lw4, const float* __restrict__ lb4,
    float* __restrict__ out)
{
    int g = blockIdx.x;
    int tid = threadIdx.x;
    __shared__ int ss, se;
    __shared__ float sg[CHN], t1[200], t2[100], t3[100];

    if (tid == 0) {
        int lo = 0, hi = NN;
        while (lo < hi) { int mid = (lo + hi) >> 1; if (batch[mid] < g) lo = mid + 1; else hi = mid; }
        ss = lo;
        lo = 0; hi = NN;
        while (lo < hi) { int mid = (lo + hi) >> 1; if (batch[mid] < g + 1) lo = mid + 1; else hi = mid; }
        se = lo;
    }
    __syncthreads();
    if (tid < CHN) {
        float sum = 0.f;
        for (int i = ss; i < se; i++) sum += feat[(size_t)i * CHN + tid];
        sg[tid] = sum / fmaxf((float)(se - ss), 1.0f);
    }
    __syncthreads();
    if (tid < 200) {
        float s = lb1[tid];
        for (int k = 0; k < 250; k++) s += sg[k] * lw1[k * 200 + tid];
        t1[tid] = fmaxf(s, 0.f);
    }
    __syncthreads();
    if (tid < 100) {
        float s = lb2[tid];
        for (int k = 0; k < 200; k++) s += t1[k] * lw2[k * 100 + tid];
        t2[tid] = fmaxf(s, 0.f);
    }
    __syncthreads();
    if (tid < 100) {
        float s = lb3[tid];
        for (int k = 0; k < 100; k++) s += t2[k] * lw3[k * 100 + tid];
        t3[tid] = fmaxf(s, 0.f);
    }
    __syncthreads();
    if (tid < 29) {
        float s = lb4[tid];
        for (int k = 0; k < 100; k++) s += t3[k] * lw4[k * 29 + tid];
        out[g * 29 + tid] = s;
    }
}

// ---------------- driver --------------------------------------------------------
extern "C" void kernel_launch(void* const* d_in, const int* in_sizes, int n_in,
                              void* d_out, int out_size)
{
    const float* x     = (const float*)d_in[0];
    const int*   ei    = (const int*)d_in[1];
    const int*   batch = (const int*)d_in[2];
    const float* W[4]    = {(const float*)d_in[3],  (const float*)d_in[7],
                            (const float*)d_in[11], (const float*)d_in[15]};
    const float* Asrc[4] = {(const float*)d_in[4],  (const float*)d_in[8],
                            (const float*)d_in[12], (const float*)d_in[16]};
    const float* Adst[4] = {(const float*)d_in[5],  (const float*)d_in[9],
                            (const float*)d_in[13], (const float*)d_in[17]};
    const float* Bb[4]   = {(const float*)d_in[6],  (const float*)d_in[10],
                            (const float*)d_in[14], (const float*)d_in[18]};
    const float* lw1 = (const float*)d_in[19]; const float* lb1 = (const float*)d_in[20];
    const float* lw2 = (const float*)d_in[21]; const float* lb2 = (const float*)d_in[22];
    const float* lw3 = (const float*)d_in[23]; const float* lb3 = (const float*)d_in[24];
    const float* lw4 = (const float*)d_in[25]; const float* lb4 = (const float*)d_in[26];
    float* out = (float*)d_out;

    float *faP;
    __half* hhP;
    __nv_bfloat16 *ahiP, *aloP, *ahi2P, *alo2P, *whiP, *wloP;
    cudaGetSymbolAddress((void**)&hhP,   g_hh);
    cudaGetSymbolAddress((void**)&faP,   g_fa);
    cudaGetSymbolAddress((void**)&ahiP,  g_ahi);
    cudaGetSymbolAddress((void**)&aloP,  g_alo);
    cudaGetSymbolAddress((void**)&ahi2P, g_ahi2);
    cudaGetSymbolAddress((void**)&alo2P, g_alo2);
    cudaGetSymbolAddress((void**)&whiP,  g_whi);
    cudaGetSymbolAddress((void**)&wloP,  g_wlo);

    cudaFuncSetAttribute(gemm_wmma_kernel,
                         cudaFuncAttributeMaxDynamicSharedMemorySize, GEMM_SMEM);

    init_kernel<<<(NN + 112 * KP2 + 255) / 256, 256>>>();
    count_kernel<<<(ET + 255) / 256, 256>>>(ei);
    scan_kernel<<<1, 1024>>>();
    scatter_kernel<<<(ET + 255) / 256, 256>>>(ei);

    split_a_kernel<<<(MPAD * KP1 + 255) / 256, 256>>>(x);
    int wtotal = NT * KP1 + 3 * NT * KP2;
    split_w_all_kernel<<<(wtotal + 255) / 256, 256>>>(W[0], W[1], W[2], W[3]);

    dim3 ggrid(MPAD / MT, 2);
    for (int l = 0; l < 4; l++) {
        const __nv_bfloat16* Ah = (l == 0) ? ahiP : ahi2P;
        const __nv_bfloat16* Al = (l == 0) ? aloP : alo2P;
        int Kpad = (l == 0) ? KP1 : KP2;
        size_t woff = (l == 0) ? 0 : (size_t)WOFF1 + (size_t)(l - 1) * NT * KP2;
        gemm_wmma_kernel<<<ggrid, 256, GEMM_SMEM>>>(
            Ah, Al, whiP + woff, wloP + woff, Kpad, Asrc[l], Adst[l], hhP);
        agg_kernel<<<NN, 128>>>(Bb[l], ahi2P, alo2P, faP, (l == 3) ? 1 : 0);
    }

    pool_mlp_kernel<<<GG, 256>>>(batch, faP, lw1, lb1, lw2, lb2, lw3, lb3, lw4, lb4, out);
}

// round 10
// speedup vs baseline: 1.3359x; 1.0684x over previous
#include <cuda_runtime.h>
#include <cuda_bf16.h>
#include <cuda_fp16.h>
#include <mma.h>
#include <cstdint>

using namespace nvcuda;

#define NN    10000
#define EE    320000
#define ET    330000
#define GG    100
#define CHN   250
#define HOUT  125
#define SLOPE 0.2f

#define MT2   64        // GEMM M tile
#define NT    256
#define MPAD  10112     // 158 * 64
#define KP1   384
#define KP2   256

// ---------------- scratch ------------------------------------------------------
__device__ __half g_hh[MPAD * 256];          // GEMM output fp16 (gather source)
__device__ float  g_fa[NN * CHN];            // layer-4 output fp32 (pool source)
__device__ float4 g_att0[NN];                // es0, ed0, es1a, ed1a  (tile by=0)
__device__ float2 g_att1[NN];                // es1b, ed1b            (tile by=1)
__device__ int    g_cnt[NN];
__device__ int    g_off[NN + 1];
__device__ int    g_pos[NN];
__device__ int    g_csr[ET];
__device__ __align__(256) __nv_bfloat16 g_ahi[MPAD * KP1];
__device__ __align__(256) __nv_bfloat16 g_alo[MPAD * KP1];
__device__ __align__(256) __nv_bfloat16 g_ahi2[MPAD * KP2];
__device__ __align__(256) __nv_bfloat16 g_alo2[MPAD * KP2];
#define WOFF1 (NT * KP1)
__device__ __align__(256) __nv_bfloat16 g_whi[NT * KP1 + 3 * NT * KP2];
__device__ __align__(256) __nv_bfloat16 g_wlo[NT * KP1 + 3 * NT * KP2];

// ---------------- helpers ------------------------------------------------------
__device__ __forceinline__ uint32_t smem_u32(const void* p) {
    uint32_t a;
    asm("{ .reg .u64 t; cvta.to.shared.u64 t, %1; cvt.u32.u64 %0, t; }" : "=r"(a) : "l"(p));
    return a;
}
__device__ __forceinline__ void cp_async16(uint32_t dst, const void* src) {
    asm volatile("cp.async.cg.shared.global [%0], [%1], 16;" :: "r"(dst), "l"(src));
}
__device__ __forceinline__ void cp_commit() { asm volatile("cp.async.commit_group;" ::: "memory"); }
__device__ __forceinline__ void cp_wait2()  { asm volatile("cp.async.wait_group 2;" ::: "memory"); }
__device__ __forceinline__ float leaky(float x) { return x > 0.f ? x : SLOPE * x; }

// ---------------- init ----------------------------------------------------------
__global__ void init_kernel() {
    int i = blockIdx.x * blockDim.x + threadIdx.x;
    if (i < NN) g_cnt[i] = 0;
    int p = i - NN;
    if (p >= 0 && p < 112 * KP2) {
        int idx = 10000 * KP2 + p;
        g_ahi2[idx] = __float2bfloat16(0.f);
        g_alo2[idx] = __float2bfloat16(0.f);
    }
}
__global__ void count_kernel(const int* __restrict__ ei) {
    int i = blockIdx.x * blockDim.x + threadIdx.x;
    if (i >= ET) return;
    int dst = (i < EE) ? ei[EE + i] : (i - EE);
    atomicAdd(&g_cnt[dst], 1);
}
__global__ void scan_kernel() {
    __shared__ int sp[1024];
    int t = threadIdx.x;
    int base = t * 10;
    int loc[10];
    int sum = 0;
#pragma unroll
    for (int i = 0; i < 10; i++) {
        int idx = base + i;
        int v = (idx < NN) ? g_cnt[idx] : 0;
        loc[i] = sum; sum += v;
    }
    sp[t] = sum;
    __syncthreads();
    for (int off = 1; off < 1024; off <<= 1) {
        int v = (t >= off) ? sp[t - off] : 0;
        __syncthreads();
        sp[t] += v;
        __syncthreads();
    }
    int pre = sp[t] - sum;
#pragma unroll
    for (int i = 0; i < 10; i++) {
        int idx = base + i;
        if (idx < NN) { int o = pre + loc[i]; g_off[idx] = o; g_pos[idx] = o; }
    }
    if (t == 1023) g_off[NN] = sp[1023];
}
__global__ void scatter_kernel(const int* __restrict__ ei) {
    int i = blockIdx.x * blockDim.x + threadIdx.x;
    if (i >= ET) return;
    int src, dst;
    if (i < EE) { src = ei[i]; dst = ei[EE + i]; }
    else        { src = i - EE; dst = i - EE; }
    int p = atomicAdd(&g_pos[dst], 1);
    g_csr[p] = src;
}

// ---------------- splits -------------------------------------------------------
__global__ void split_a_kernel(const float* __restrict__ in) {
    int idx = blockIdx.x * blockDim.x + threadIdx.x;
    if (idx >= MPAD * KP1) return;
    int r = idx / KP1, k = idx - r * KP1;
    float v = (r < NN && k < 336) ? in[(size_t)r * 336 + k] : 0.f;
    __nv_bfloat16 h = __float2bfloat16(v);
    __nv_bfloat16 l = __float2bfloat16(v - __bfloat162float(h));
    g_ahi[idx] = h; g_alo[idx] = l;
}
__global__ void split_w_all_kernel(const float* __restrict__ W1, const float* __restrict__ W2,
                                   const float* __restrict__ W3, const float* __restrict__ W4)
{
    int idx = blockIdx.x * blockDim.x + threadIdx.x;
    int total = NT * KP1 + 3 * NT * KP2;
    if (idx >= total) return;
    const float* W; int K, Kpad, rem;
    if (idx < NT * KP1) { W = W1; K = 336; Kpad = KP1; rem = idx; }
    else {
        int idx2 = idx - NT * KP1;
        int l = idx2 / (NT * KP2);
        rem = idx2 - l * (NT * KP2);
        W = (l == 0) ? W2 : (l == 1) ? W3 : W4;
        K = 250; Kpad = KP2;
    }
    int n = rem / Kpad, k = rem - n * Kpad;
    float v = (n < CHN && k < K) ? W[(size_t)k * CHN + n] : 0.f;
    __nv_bfloat16 h = __float2bfloat16(v);
    __nv_bfloat16 l = __float2bfloat16(v - __bfloat162float(h));
    g_whi[idx] = h; g_wlo[idx] = l;
}

// ---------------- WMMA GEMM: 64x128 tile, 4-stage cp.async, 1 barrier/iter ------
#define ALD   40
#define BLD   40
#define A_ELE (64 * ALD)          // 2560 bf16
#define B_ELE (128 * BLD)         // 5120 bf16
#define STG_ELE (A_ELE + B_ELE)   // 7680 bf16 = 15360 B
#define CLD   136
#define GEMM_SMEM (4 * STG_ELE * 2)   // 61440 B (Cs 64*136*4=34816 reuses it)

__global__ __launch_bounds__(256) void gemm_wmma_kernel(
    const __nv_bfloat16* __restrict__ Ahi, const __nv_bfloat16* __restrict__ Alo,
    const __nv_bfloat16* __restrict__ Bhi, const __nv_bfloat16* __restrict__ Blo,
    int Kpad,
    const float* __restrict__ asrc, const float* __restrict__ adst,
    __half* __restrict__ hout)
{
    extern __shared__ char smem[];
    float* Cs = (float*)smem;
    __shared__ float s_as[128], s_ad[128];

    int tid = threadIdx.x;
    int wid = tid >> 5;
    int wm = wid >> 2, wn = wid & 3;       // warp tile 32x32 at (wm*32, wn*32)
    int m0 = blockIdx.x * MT2;
    int by = blockIdx.y;
    int n0 = by * 128;

    if (tid < 128) {
        int col = n0 + tid;
        s_as[tid] = (col < CHN) ? asrc[col] : 0.f;
        s_ad[tid] = (col < CHN) ? adst[col] : 0.f;
    }

    uint32_t sbase = smem_u32(smem);
    int niter = (3 * Kpad) >> 5;           // >= 24 always

    auto load_stage = [&](int st, int kb) {
        int kp = kb << 5;
        int seg = kp / Kpad;
        int kk = kp - seg * Kpad;
        const __nv_bfloat16* aseg = (seg < 2) ? Ahi : Alo;
        const __nv_bfloat16* bseg = (seg == 1) ? Blo : Bhi;
        uint32_t stb = sbase + st * STG_ELE * 2;
        // A: 64 rows x 32 cols = 256 x 16B chunks, one per thread
        {
            int rowa = tid >> 2, grpa = tid & 3;
            cp_async16(stb + (rowa * ALD + grpa * 8) * 2,
                       aseg + (size_t)(m0 + rowa) * Kpad + kk + grpa * 8);
        }
        // B: 128 rows x 32 cols = 512 chunks, two per thread
#pragma unroll
        for (int i = 0; i < 2; i++) {
            int c = tid + i * 256;
            int rowb = c >> 2, grpb = c & 3;
            cp_async16(stb + (A_ELE + rowb * BLD + grpb * 8) * 2,
                       bseg + (size_t)(n0 + rowb) * Kpad + kk + grpb * 8);
        }
        cp_commit();
    };

    wmma::fragment<wmma::accumulator, 16, 16, 16, float> c[2][2];
#pragma unroll
    for (int i = 0; i < 2; i++)
#pragma unroll
        for (int j = 0; j < 2; j++) wmma::fill_fragment(c[i][j], 0.f);

    load_stage(0, 0);
    load_stage(1, 1);
    load_stage(2, 2);

    for (int kb = 0; kb < niter; kb++) {
        cp_wait2();            // stage kb complete (2 groups may remain pending)
        __syncthreads();       // all threads' copies visible; all done reading stage (kb+3)&3
        if (kb + 3 < niter) load_stage((kb + 3) & 3, kb + 3);
        else                cp_commit();   // keep group count in lockstep

        const __nv_bfloat16* stg = (const __nv_bfloat16*)(smem + (size_t)(kb & 3) * STG_ELE * 2);
        const __nv_bfloat16* at = stg + wm * 32 * ALD;
        const __nv_bfloat16* bt = stg + A_ELE + wn * 32 * BLD;
#pragma unroll
        for (int ks = 0; ks < 2; ks++) {
            wmma::fragment<wmma::matrix_a, 16, 16, 16, __nv_bfloat16, wmma::row_major> a0, a1;
            wmma::load_matrix_sync(a0, at + ks * 16, ALD);
            wmma::load_matrix_sync(a1, at + 16 * ALD + ks * 16, ALD);
            wmma::fragment<wmma::matrix_b, 16, 16, 16, __nv_bfloat16, wmma::col_major> b0, b1;
            wmma::load_matrix_sync(b0, bt + ks * 16, BLD);
            wmma::load_matrix_sync(b1, bt + 16 * BLD + ks * 16, BLD);
            wmma::mma_sync(c[0][0], a0, b0, c[0][0]);
            wmma::mma_sync(c[0][1], a0, b1, c[0][1]);
            wmma::mma_sync(c[1][0], a1, b0, c[1][0]);
            wmma::mma_sync(c[1][1], a1, b1, c[1][1]);
        }
    }
    __syncthreads();

    // epilogue: frags -> Cs (overlays stage memory; all compute done)
#pragma unroll
    for (int i = 0; i < 2; i++)
#pragma unroll
        for (int j = 0; j < 2; j++)
            wmma::store_matrix_sync(Cs + (wm * 32 + i * 16) * CLD + wn * 32 + j * 16,
                                    c[i][j], CLD, wmma::mem_row_major);
    __syncthreads();

    // coalesced fp16 store (stride 256)
#pragma unroll
    for (int it = 0; it < 16; it++) {
        int idx = it * 256 + tid;          // 4096 half2 slots
        int r = idx >> 6, c2 = idx & 63;
        int grow = m0 + r, gcol = n0 + 2 * c2;
        if (grow < NN && gcol < CHN) {
            float v0 = Cs[r * CLD + 2 * c2];
            float v1 = Cs[r * CLD + 2 * c2 + 1];
            *(__half2*)(hout + (size_t)grow * 256 + gcol) = __floats2half2_rn(v0, v1);
        }
    }

    // fused attention dots: 2 threads per row (64 rows)
    if (tid < 128) {
        int r = tid >> 1;
        int half = tid & 1;
        int ccb = half * 64;
        float s0 = 0.f, d0 = 0.f, s1 = 0.f, d1 = 0.f;
#pragma unroll 8
        for (int q = 0; q < 64; q++) {
            int cc = ccb + q;
            float v = Cs[r * CLD + cc];
            float a = s_as[cc], bvd = s_ad[cc];
            if (n0 + cc < HOUT) { s0 += v * a; d0 += v * bvd; }
            else                { s1 += v * a; d1 += v * bvd; }
        }
        s0 += __shfl_xor_sync(0xffffffffu, s0, 1);
        d0 += __shfl_xor_sync(0xffffffffu, d0, 1);
        s1 += __shfl_xor_sync(0xffffffffu, s1, 1);
        d1 += __shfl_xor_sync(0xffffffffu, d1, 1);
        int grow = m0 + r;
        if (half == 0 && grow < NN) {
            if (by == 0) g_att0[grow] = make_float4(s0, d0, s1, d1);
            else         g_att1[grow] = make_float2(s1, d1);
        }
    }
}

// ---------------- aggregation: single-pass softmax (deg<=128) + fp16 gather -----
__global__ __launch_bounds__(128) void agg_kernel(const float* __restrict__ bias,
                                                  __nv_bfloat16* __restrict__ ohi,
                                                  __nv_bfloat16* __restrict__ olo,
                                                  float* __restrict__ of32,
                                                  int f32out)
{
    int i = blockIdx.x;
    int tid = threadIdx.x;
    int lane = tid & 31, warp = tid >> 5;

    __shared__ float w0[4], w1[4];
    __shared__ int   s_src[128];
    __shared__ float s_a0[128], s_a1[128];

    int s = g_off[i], e = g_off[i + 1];
    int d = e - s;
    float4 a0i = g_att0[i];
    float2 a1i = g_att1[i];
    float ed0 = a0i.y, ed1 = a0i.w + a1i.y;

    float acc0 = 0.f, acc1 = 0.f;
    int c0 = 2 * tid;
    bool act = (tid < HOUT);
    bool head0a = (c0 < HOUT);
    bool head0b = (c0 + 1 < HOUT);

    if (d <= 128) {
        // ---- fast path: one edge per thread, logits computed exactly once ----
        bool valid = tid < d;
        int src = 0;
        float l0 = -1e30f, l1 = -1e30f;
        if (valid) {
            src = g_csr[s + tid];
            float4 b0 = g_att0[src]; float2 b1 = g_att1[src];
            l0 = leaky(b0.x + ed0);
            l1 = leaky(b0.z + b1.x + ed1);
        }
        float m0 = l0, m1 = l1;
#pragma unroll
        for (int o = 16; o; o >>= 1) {
            m0 = fmaxf(m0, __shfl_xor_sync(0xffffffffu, m0, o));
            m1 = fmaxf(m1, __shfl_xor_sync(0xffffffffu, m1, o));
        }
        if (lane == 0) { w0[warp] = m0; w1[warp] = m1; }
        __syncthreads();
        m0 = fmaxf(fmaxf(w0[0], w0[1]), fmaxf(w0[2], w0[3]));
        m1 = fmaxf(fmaxf(w1[0], w1[1]), fmaxf(w1[2], w1[3]));
        __syncthreads();

        float p0 = valid ? __expf(l0 - m0) : 0.f;
        float p1 = valid ? __expf(l1 - m1) : 0.f;
        float d0 = p0, d1 = p1;
#pragma unroll
        for (int o = 16; o; o >>= 1) {
            d0 += __shfl_xor_sync(0xffffffffu, d0, o);
            d1 += __shfl_xor_sync(0xffffffffu, d1, o);
        }
        if (lane == 0) { w0[warp] = d0; w1[warp] = d1; }
        __syncthreads();
        d0 = w0[0] + w0[1] + w0[2] + w0[3] + 1e-16f;
        d1 = w1[0] + w1[1] + w1[2] + w1[3] + 1e-16f;
        float r0 = 1.0f / d0, r1 = 1.0f / d1;

        s_src[tid] = src;
        s_a0[tid] = p0 * r0;
        s_a1[tid] = p1 * r1;
        __syncthreads();

        if (act) {
#pragma unroll 4
            for (int k = 0; k < d; k++) {
                int sk = s_src[k];
                __half2 hv2 = *(const __half2*)(g_hh + (size_t)sk * 256 + c0);
                float2 hv = __half22float2(hv2);
                float aa = head0a ? s_a0[k] : s_a1[k];
                float ab = head0b ? s_a0[k] : s_a1[k];
                acc0 += aa * hv.x;
                acc1 += ab * hv.y;
            }
        }
    } else {
        // ---- fallback: 3-pass (degree > 128; practically never) ----
        float m0 = -1e30f, m1 = -1e30f;
        for (int j = s + tid; j < e; j += 128) {
            int src = g_csr[j];
            float4 b0 = g_att0[src]; float2 b1 = g_att1[src];
            m0 = fmaxf(m0, leaky(b0.x + ed0));
            m1 = fmaxf(m1, leaky(b0.z + b1.x + ed1));
        }
#pragma unroll
        for (int o = 16; o; o >>= 1) {
            m0 = fmaxf(m0, __shfl_xor_sync(0xffffffffu, m0, o));
            m1 = fmaxf(m1, __shfl_xor_sync(0xffffffffu, m1, o));
        }
        if (lane == 0) { w0[warp] = m0; w1[warp] = m1; }
        __syncthreads();
        m0 = fmaxf(fmaxf(w0[0], w0[1]), fmaxf(w0[2], w0[3]));
        m1 = fmaxf(fmaxf(w1[0], w1[1]), fmaxf(w1[2], w1[3]));
        __syncthreads();

        float d0 = 0.f, d1 = 0.f;
        for (int j = s + tid; j < e; j += 128) {
            int src = g_csr[j];
            float4 b0 = g_att0[src]; float2 b1 = g_att1[src];
            d0 += __expf(leaky(b0.x + ed0) - m0);
            d1 += __expf(leaky(b0.z + b1.x + ed1) - m1);
        }
#pragma unroll
        for (int o = 16; o; o >>= 1) {
            d0 += __shfl_xor_sync(0xffffffffu, d0, o);
            d1 += __shfl_xor_sync(0xffffffffu, d1, o);
        }
        if (lane == 0) { w0[warp] = d0; w1[warp] = d1; }
        __syncthreads();
        d0 = w0[0] + w0[1] + w0[2] + w0[3] + 1e-16f;
        d1 = w1[0] + w1[1] + w1[2] + w1[3] + 1e-16f;
        float r0 = 1.0f / d0, r1 = 1.0f / d1;

        for (int base = s; base < e; base += 128) {
            int j = base + tid;
            if (j < e) {
                int src = g_csr[j];
                float4 b0 = g_att0[src]; float2 b1 = g_att1[src];
                s_src[tid] = src;
                s_a0[tid] = __expf(leaky(b0.x + ed0) - m0) * r0;
                s_a1[tid] = __expf(leaky(b0.z + b1.x + ed1) - m1) * r1;
            }
            __syncthreads();
            int cnt = min(128, e - base);
            if (act) {
#pragma unroll 4
                for (int k = 0; k < cnt; k++) {
                    int sk = s_src[k];
                    __half2 hv2 = *(const __half2*)(g_hh + (size_t)sk * 256 + c0);
                    float2 hv = __half22float2(hv2);
                    float aa = head0a ? s_a0[k] : s_a1[k];
                    float ab = head0b ? s_a0[k] : s_a1[k];
                    acc0 += aa * hv.x;
                    acc1 += ab * hv.y;
                }
            }
            __syncthreads();
        }
    }

    if (f32out) {
        if (act) {
            float v0 = fmaxf(acc0 + bias[c0], 0.f);
            float v1 = fmaxf(acc1 + bias[c0 + 1], 0.f);
            of32[(size_t)i * CHN + c0]     = v0;
            of32[(size_t)i * CHN + c0 + 1] = v1;
        }
    } else {
        size_t o = (size_t)i * KP2 + c0;
        if (act) {
            float v0 = fmaxf(acc0 + bias[c0], 0.f);
            float v1 = fmaxf(acc1 + bias[c0 + 1], 0.f);
            __nv_bfloat16 h0 = __float2bfloat16(v0);
            __nv_bfloat16 h1 = __float2bfloat16(v1);
            __nv_bfloat16 l0 = __float2bfloat16(v0 - __bfloat162float(h0));
            __nv_bfloat16 l1 = __float2bfloat16(v1 - __bfloat162float(h1));
            *(__nv_bfloat162*)(ohi + o) = __nv_bfloat162(h0, h1);
            *(__nv_bfloat162*)(olo + o) = __nv_bfloat162(l0, l1);
        } else {
            __nv_bfloat162 z(__float2bfloat16(0.f), __float2bfloat16(0.f));
            *(__nv_bfloat162*)(ohi + o) = z;
            *(__nv_bfloat162*)(olo + o) = z;
        }
    }
}

// ---------------- fused pool + 4-layer MLP (one block per graph) ---------------
__global__ __launch_bounds__(256) void pool_mlp_kernel(
    const int* __restrict__ batch, const float* __restrict__ feat,
    const float* __restrict__ lw1, const float* __restrict__ lb1,
    const float* __restrict__ lw2, const float* __restrict__ lb2,
    const float* __restrict__ lw3, const float* __restrict__ lb3,
    const float* __restrict__ lw4, const float* __restrict__ lb4,
    float* __restrict__ out)
{
    int g = blockIdx.x;
    int tid = threadIdx.x;
    __shared__ int ss, se;
    __shared__ float sg[CHN], t1[200], t2[100], t3[100];

    if (tid == 0) {
        int lo = 0, hi = NN;
        while (lo < hi) { int mid = (lo + hi) >> 1; if (batch[mid] < g) lo = mid + 1; else hi = mid; }
        ss = lo;
        lo = 0; hi = NN;
        while (lo < hi) { int mid = (lo + hi) >> 1; if (batch[mid] < g + 1) lo = mid + 1; else hi = mid; }
        se = lo;
    }
    __syncthreads();
    if (tid < CHN) {
        float sum = 0.f;
        for (int i = ss; i < se; i++) sum += feat[(size_t)i * CHN + tid];
        sg[tid] = sum / fmaxf((float)(se - ss), 1.0f);
    }
    __syncthreads();
    if (tid < 200) {
        float s = lb1[tid];
        for (int k = 0; k < 250; k++) s += sg[k] * lw1[k * 200 + tid];
        t1[tid] = fmaxf(s, 0.f);
    }
    __syncthreads();
    if (tid < 100) {
        float s = lb2[tid];
        for (int k = 0; k < 200; k++) s += t1[k] * lw2[k * 100 + tid];
        t2[tid] = fmaxf(s, 0.f);
    }
    __syncthreads();
    if (tid < 100) {
        float s = lb3[tid];
        for (int k = 0; k < 100; k++) s += t2[k] * lw3[k * 100 + tid];
        t3[tid] = fmaxf(s, 0.f);
    }
    __syncthreads();
    if (tid < 29) {
        float s = lb4[tid];
        for (int k = 0; k < 100; k++) s += t3[k] * lw4[k * 29 + tid];
        out[g * 29 + tid] = s;
    }
}

// ---------------- driver --------------------------------------------------------
extern "C" void kernel_launch(void* const* d_in, const int* in_sizes, int n_in,
                              void* d_out, int out_size)
{
    const float* x     = (const float*)d_in[0];
    const int*   ei    = (const int*)d_in[1];
    const int*   batch = (const int*)d_in[2];
    const float* W[4]    = {(const float*)d_in[3],  (const float*)d_in[7],
                            (const float*)d_in[11], (const float*)d_in[15]};
    const float* Asrc[4] = {(const float*)d_in[4],  (const float*)d_in[8],
                            (const float*)d_in[12], (const float*)d_in[16]};
    const float* Adst[4] = {(const float*)d_in[5],  (const float*)d_in[9],
                            (const float*)d_in[13], (const float*)d_in[17]};
    const float* Bb[4]   = {(const float*)d_in[6],  (const float*)d_in[10],
                            (const float*)d_in[14], (const float*)d_in[18]};
    const float* lw1 = (const float*)d_in[19]; const float* lb1 = (const float*)d_in[20];
    const float* lw2 = (const float*)d_in[21]; const float* lb2 = (const float*)d_in[22];
    const float* lw3 = (const float*)d_in[23]; const float* lb3 = (const float*)d_in[24];
    const float* lw4 = (const float*)d_in[25]; const float* lb4 = (const float*)d_in[26];
    float* out = (float*)d_out;

    float *faP;
    __half* hhP;
    __nv_bfloat16 *ahiP, *aloP, *ahi2P, *alo2P, *whiP, *wloP;
    cudaGetSymbolAddress((void**)&hhP,   g_hh);
    cudaGetSymbolAddress((void**)&faP,   g_fa);
    cudaGetSymbolAddress((void**)&ahiP,  g_ahi);
    cudaGetSymbolAddress((void**)&aloP,  g_alo);
    cudaGetSymbolAddress((void**)&ahi2P, g_ahi2);
    cudaGetSymbolAddress((void**)&alo2P, g_alo2);
    cudaGetSymbolAddress((void**)&whiP,  g_whi);
    cudaGetSymbolAddress((void**)&wloP,  g_wlo);

    cudaFuncSetAttribute(gemm_wmma_kernel,
                         cudaFuncAttributeMaxDynamicSharedMemorySize, GEMM_SMEM);

    init_kernel<<<(NN + 112 * KP2 + 255) / 256, 256>>>();
    count_kernel<<<(ET + 255) / 256, 256>>>(ei);
    scan_kernel<<<1, 1024>>>();
    scatter_kernel<<<(ET + 255) / 256, 256>>>(ei);

    split_a_kernel<<<(MPAD * KP1 + 255) / 256, 256>>>(x);
    int wtotal = NT * KP1 + 3 * NT * KP2;
    split_w_all_kernel<<<(wtotal + 255) / 256, 256>>>(W[0], W[1], W[2], W[3]);

    dim3 ggrid(MPAD / MT2, 2);
    for (int l = 0; l < 4; l++) {
        const __nv_bfloat16* Ah = (l == 0) ? ahiP : ahi2P;
        const __nv_bfloat16* Al = (l == 0) ? aloP : alo2P;
        int Kpad = (l == 0) ? KP1 : KP2;
        size_t woff = (l == 0) ? 0 : (size_t)WOFF1 + (size_t)(l - 1) * NT * KP2;
        gemm_wmma_kernel<<<ggrid, 256, GEMM_SMEM>>>(
            Ah, Al, whiP + woff, wloP + woff, Kpad, Asrc[l], Adst[l], hhP);
        agg_kernel<<<NN, 128>>>(Bb[l], ahi2P, alo2P, faP, (l == 3) ? 1 : 0);
    }

    pool_mlp_kernel<<<GG, 256>>>(batch, faP, lw1, lb1, lw2, lb2, lw3, lb3, lw4, lb4, out);
}

// round 11
// speedup vs baseline: 1.6082x; 1.2038x over previous
#include <cuda_runtime.h>
#include <cuda_fp16.h>
#include <mma.h>
#include <cstdint>

using namespace nvcuda;

#define NN    10000
#define EE    320000
#define ET    330000
#define GG    100
#define CHN   250
#define HOUT  125
#define SLOPE 0.2f

#define MT2   64        // GEMM M tile
#define NT    256
#define MPAD  10112     // 158 * 64
#define KP1   384
#define KP2   256

// ---------------- scratch ------------------------------------------------------
__device__ __half g_hh[MPAD * 256];          // GEMM output fp16 (gather source)
__device__ __half g_a2h[MPAD * 256];         // layers 2-4 GEMM A input fp16 (agg-written)
__device__ float  g_fa[NN * CHN];            // layer-4 output fp32 (pool source)
__device__ float4 g_att0[NN];
__device__ float2 g_att1[NN];
__device__ int    g_cnt[NN];
__device__ int    g_off[NN + 1];
__device__ int    g_pos[NN];
__device__ int    g_csr[ET];
__device__ __align__(256) __half g_a1h[MPAD * KP1];   // layer1 A fp16
#define WOFF1 (NT * KP1)
__device__ __align__(256) __half g_wh[NT * KP1 + 3 * NT * KP2];
__device__ __align__(256) __half g_wl[NT * KP1 + 3 * NT * KP2];

// ---------------- helpers ------------------------------------------------------
__device__ __forceinline__ uint32_t smem_u32(const void* p) {
    uint32_t a;
    asm("{ .reg .u64 t; cvta.to.shared.u64 t, %1; cvt.u32.u64 %0, t; }" : "=r"(a) : "l"(p));
    return a;
}
__device__ __forceinline__ void cp_async16(uint32_t dst, const void* src) {
    asm volatile("cp.async.cg.shared.global [%0], [%1], 16;" :: "r"(dst), "l"(src));
}
__device__ __forceinline__ void cp_commit() { asm volatile("cp.async.commit_group;" ::: "memory"); }
__device__ __forceinline__ void cp_wait2()  { asm volatile("cp.async.wait_group 2;" ::: "memory"); }
__device__ __forceinline__ float leaky(float x) { return x > 0.f ? x : SLOPE * x; }

// ---------------- init ----------------------------------------------------------
__global__ void init_kernel() {
    int i = blockIdx.x * blockDim.x + threadIdx.x;
    if (i < NN) g_cnt[i] = 0;
    int p = i - NN;
    if (p >= 0 && p < 112 * KP2) {
        g_a2h[10000 * KP2 + p] = __float2half(0.f);
    }
}
__global__ void count_kernel(const int* __restrict__ ei) {
    int i = blockIdx.x * blockDim.x + threadIdx.x;
    if (i >= ET) return;
    int dst = (i < EE) ? ei[EE + i] : (i - EE);
    atomicAdd(&g_cnt[dst], 1);
}
__global__ void scan_kernel() {
    __shared__ int sp[1024];
    int t = threadIdx.x;
    int base = t * 10;
    int loc[10];
    int sum = 0;
#pragma unroll
    for (int i = 0; i < 10; i++) {
        int idx = base + i;
        int v = (idx < NN) ? g_cnt[idx] : 0;
        loc[i] = sum; sum += v;
    }
    sp[t] = sum;
    __syncthreads();
    for (int off = 1; off < 1024; off <<= 1) {
        int v = (t >= off) ? sp[t - off] : 0;
        __syncthreads();
        sp[t] += v;
        __syncthreads();
    }
    int pre = sp[t] - sum;
#pragma unroll
    for (int i = 0; i < 10; i++) {
        int idx = base + i;
        if (idx < NN) { int o = pre + loc[i]; g_off[idx] = o; g_pos[idx] = o; }
    }
    if (t == 1023) g_off[NN] = sp[1023];
}
__global__ void scatter_kernel(const int* __restrict__ ei) {
    int i = blockIdx.x * blockDim.x + threadIdx.x;
    if (i >= ET) return;
    int src, dst;
    if (i < EE) { src = ei[i]; dst = ei[EE + i]; }
    else        { src = i - EE; dst = i - EE; }
    int p = atomicAdd(&g_pos[dst], 1);
    g_csr[p] = src;
}

// ---------------- splits -------------------------------------------------------
__global__ void split_a_kernel(const float* __restrict__ in) {
    int idx = blockIdx.x * blockDim.x + threadIdx.x;
    if (idx >= MPAD * KP1) return;
    int r = idx / KP1, k = idx - r * KP1;
    float v = (r < NN && k < 336) ? in[(size_t)r * 336 + k] : 0.f;
    g_a1h[idx] = __float2half(v);
}
__global__ void split_w_all_kernel(const float* __restrict__ W1, const float* __restrict__ W2,
                                   const float* __restrict__ W3, const float* __restrict__ W4)
{
    int idx = blockIdx.x * blockDim.x + threadIdx.x;
    int total = NT * KP1 + 3 * NT * KP2;
    if (idx >= total) return;
    const float* W; int K, Kpad, rem;
    if (idx < NT * KP1) { W = W1; K = 336; Kpad = KP1; rem = idx; }
    else {
        int idx2 = idx - NT * KP1;
        int l = idx2 / (NT * KP2);
        rem = idx2 - l * (NT * KP2);
        W = (l == 0) ? W2 : (l == 1) ? W3 : W4;
        K = 250; Kpad = KP2;
    }
    int n = rem / Kpad, k = rem - n * Kpad;
    float v = (n < CHN && k < K) ? W[(size_t)k * CHN + n] : 0.f;
    __half h = __float2half(v);
    __half l = __float2half(v - __half2float(h));
    g_wh[idx] = h; g_wl[idx] = l;
}

// ---------------- WMMA fp16 GEMM: 64x128 tile, K' = 2*Kpad (W hi/lo) -----------
#define ALD   40
#define BLD   40
#define A_ELE (64 * ALD)
#define B_ELE (128 * BLD)
#define STG_ELE (A_ELE + B_ELE)   // 7680 halves = 15360 B
#define CLD   136
#define GEMM_SMEM (4 * STG_ELE * 2)

__global__ __launch_bounds__(256) void gemm_wmma_kernel(
    const __half* __restrict__ Ain,
    const __half* __restrict__ Bhi, const __half* __restrict__ Blo,
    int Kpad,
    const float* __restrict__ asrc, const float* __restrict__ adst,
    __half* __restrict__ hout)
{
    extern __shared__ char smem[];
    float* Cs = (float*)smem;
    __shared__ float s_as[128], s_ad[128];

    int tid = threadIdx.x;
    int wid = tid >> 5;
    int wm = wid >> 2, wn = wid & 3;
    int m0 = blockIdx.x * MT2;
    int by = blockIdx.y;
    int n0 = by * 128;

    if (tid < 128) {
        int col = n0 + tid;
        s_as[tid] = (col < CHN) ? asrc[col] : 0.f;
        s_ad[tid] = (col < CHN) ? adst[col] : 0.f;
    }

    uint32_t sbase = smem_u32(smem);
    int niter = (2 * Kpad) >> 5;           // 24 (l1) / 16 (l2-4)

    auto load_stage = [&](int st, int kb) {
        int kp = kb << 5;
        int seg = kp / Kpad;
        int kk = kp - seg * Kpad;
        const __half* bseg = (seg == 0) ? Bhi : Blo;
        uint32_t stb = sbase + st * STG_ELE * 2;
        {
            int rowa = tid >> 2, grpa = tid & 3;
            cp_async16(stb + (rowa * ALD + grpa * 8) * 2,
                       Ain + (size_t)(m0 + rowa) * Kpad + kk + grpa * 8);
        }
#pragma unroll
        for (int i = 0; i < 2; i++) {
            int c = tid + i * 256;
            int rowb = c >> 2, grpb = c & 3;
            cp_async16(stb + (A_ELE + rowb * BLD + grpb * 8) * 2,
                       bseg + (size_t)(n0 + rowb) * Kpad + kk + grpb * 8);
        }
        cp_commit();
    };

    wmma::fragment<wmma::accumulator, 16, 16, 16, float> c[2][2];
#pragma unroll
    for (int i = 0; i < 2; i++)
#pragma unroll
        for (int j = 0; j < 2; j++) wmma::fill_fragment(c[i][j], 0.f);

    load_stage(0, 0);
    load_stage(1, 1);
    load_stage(2, 2);

    for (int kb = 0; kb < niter; kb++) {
        cp_wait2();
        __syncthreads();
        if (kb + 3 < niter) load_stage((kb + 3) & 3, kb + 3);
        else                cp_commit();

        const __half* stg = (const __half*)(smem + (size_t)(kb & 3) * STG_ELE * 2);
        const __half* at = stg + wm * 32 * ALD;
        const __half* bt = stg + A_ELE + wn * 32 * BLD;
#pragma unroll
        for (int ks = 0; ks < 2; ks++) {
            wmma::fragment<wmma::matrix_a, 16, 16, 16, __half, wmma::row_major> a0, a1;
            wmma::load_matrix_sync(a0, at + ks * 16, ALD);
            wmma::load_matrix_sync(a1, at + 16 * ALD + ks * 16, ALD);
            wmma::fragment<wmma::matrix_b, 16, 16, 16, __half, wmma::col_major> b0, b1;
            wmma::load_matrix_sync(b0, bt + ks * 16, BLD);
            wmma::load_matrix_sync(b1, bt + 16 * BLD + ks * 16, BLD);
            wmma::mma_sync(c[0][0], a0, b0, c[0][0]);
            wmma::mma_sync(c[0][1], a0, b1, c[0][1]);
            wmma::mma_sync(c[1][0], a1, b0, c[1][0]);
            wmma::mma_sync(c[1][1], a1, b1, c[1][1]);
        }
    }
    __syncthreads();

#pragma unroll
    for (int i = 0; i < 2; i++)
#pragma unroll
        for (int j = 0; j < 2; j++)
            wmma::store_matrix_sync(Cs + (wm * 32 + i * 16) * CLD + wn * 32 + j * 16,
                                    c[i][j], CLD, wmma::mem_row_major);
    __syncthreads();

    // coalesced fp16 store (stride 256)
#pragma unroll
    for (int it = 0; it < 16; it++) {
        int idx = it * 256 + tid;
        int r = idx >> 6, c2 = idx & 63;
        int grow = m0 + r, gcol = n0 + 2 * c2;
        if (grow < NN && gcol < CHN) {
            float v0 = Cs[r * CLD + 2 * c2];
            float v1 = Cs[r * CLD + 2 * c2 + 1];
            *(__half2*)(hout + (size_t)grow * 256 + gcol) = __floats2half2_rn(v0, v1);
        }
    }

    // fused attention dots
    if (tid < 128) {
        int r = tid >> 1;
        int half = tid & 1;
        int ccb = half * 64;
        float s0 = 0.f, d0 = 0.f, s1 = 0.f, d1 = 0.f;
#pragma unroll 8
        for (int q = 0; q < 64; q++) {
            int cc = ccb + q;
            float v = Cs[r * CLD + cc];
            float a = s_as[cc], bvd = s_ad[cc];
            if (n0 + cc < HOUT) { s0 += v * a; d0 += v * bvd; }
            else                { s1 += v * a; d1 += v * bvd; }
        }
        s0 += __shfl_xor_sync(0xffffffffu, s0, 1);
        d0 += __shfl_xor_sync(0xffffffffu, d0, 1);
        s1 += __shfl_xor_sync(0xffffffffu, s1, 1);
        d1 += __shfl_xor_sync(0xffffffffu, d1, 1);
        int grow = m0 + r;
        if (half == 0 && grow < NN) {
            if (by == 0) g_att0[grow] = make_float4(s0, d0, s1, d1);
            else         g_att1[grow] = make_float2(s1, d1);
        }
    }
}

// ---------------- aggregation: single-pass softmax + fp16 gather ----------------
__global__ __launch_bounds__(128) void agg_kernel(const float* __restrict__ bias,
                                                  __half* __restrict__ oh,
                                                  float* __restrict__ of32,
                                                  int f32out)
{
    int i = blockIdx.x;
    int tid = threadIdx.x;
    int lane = tid & 31, warp = tid >> 5;

    __shared__ float w0[4], w1[4];
    __shared__ int   s_src[128];
    __shared__ float s_a0[128], s_a1[128];

    int s = g_off[i], e = g_off[i + 1];
    int d = e - s;
    float4 a0i = g_att0[i];
    float2 a1i = g_att1[i];
    float ed0 = a0i.y, ed1 = a0i.w + a1i.y;

    float acc0 = 0.f, acc1 = 0.f;
    int c0 = 2 * tid;
    bool act = (tid < HOUT);
    bool head0a = (c0 < HOUT);
    bool head0b = (c0 + 1 < HOUT);

    if (d <= 128) {
        bool valid = tid < d;
        int src = 0;
        float l0 = -1e30f, l1 = -1e30f;
        if (valid) {
            src = g_csr[s + tid];
            float4 b0 = g_att0[src]; float2 b1 = g_att1[src];
            l0 = leaky(b0.x + ed0);
            l1 = leaky(b0.z + b1.x + ed1);
        }
        float m0 = l0, m1 = l1;
#pragma unroll
        for (int o = 16; o; o >>= 1) {
            m0 = fmaxf(m0, __shfl_xor_sync(0xffffffffu, m0, o));
            m1 = fmaxf(m1, __shfl_xor_sync(0xffffffffu, m1, o));
        }
        if (lane == 0) { w0[warp] = m0; w1[warp] = m1; }
        __syncthreads();
        m0 = fmaxf(fmaxf(w0[0], w0[1]), fmaxf(w0[2], w0[3]));
        m1 = fmaxf(fmaxf(w1[0], w1[1]), fmaxf(w1[2], w1[3]));
        __syncthreads();

        float p0 = valid ? __expf(l0 - m0) : 0.f;
        float p1 = valid ? __expf(l1 - m1) : 0.f;
        float d0 = p0, d1 = p1;
#pragma unroll
        for (int o = 16; o; o >>= 1) {
            d0 += __shfl_xor_sync(0xffffffffu, d0, o);
            d1 += __shfl_xor_sync(0xffffffffu, d1, o);
        }
        if (lane == 0) { w0[warp] = d0; w1[warp] = d1; }
        __syncthreads();
        d0 = w0[0] + w0[1] + w0[2] + w0[3] + 1e-16f;
        d1 = w1[0] + w1[1] + w1[2] + w1[3] + 1e-16f;
        float r0 = 1.0f / d0, r1 = 1.0f / d1;

        s_src[tid] = src;
        s_a0[tid] = p0 * r0;
        s_a1[tid] = p1 * r1;
        __syncthreads();

        if (act) {
#pragma unroll 4
            for (int k = 0; k < d; k++) {
                int sk = s_src[k];
                __half2 hv2 = *(const __half2*)(g_hh + (size_t)sk * 256 + c0);
                float2 hv = __half22float2(hv2);
                float aa = head0a ? s_a0[k] : s_a1[k];
                float ab = head0b ? s_a0[k] : s_a1[k];
                acc0 += aa * hv.x;
                acc1 += ab * hv.y;
            }
        }
    } else {
        // fallback 3-pass for degree > 128
        float m0 = -1e30f, m1 = -1e30f;
        for (int j = s + tid; j < e; j += 128) {
            int src = g_csr[j];
            float4 b0 = g_att0[src]; float2 b1 = g_att1[src];
            m0 = fmaxf(m0, leaky(b0.x + ed0));
            m1 = fmaxf(m1, leaky(b0.z + b1.x + ed1));
        }
#pragma unroll
        for (int o = 16; o; o >>= 1) {
            m0 = fmaxf(m0, __shfl_xor_sync(0xffffffffu, m0, o));
            m1 = fmaxf(m1, __shfl_xor_sync(0xffffffffu, m1, o));
        }
        if (lane == 0) { w0[warp] = m0; w1[warp] = m1; }
        __syncthreads();
        m0 = fmaxf(fmaxf(w0[0], w0[1]), fmaxf(w0[2], w0[3]));
        m1 = fmaxf(fmaxf(w1[0], w1[1]), fmaxf(w1[2], w1[3]));
        __syncthreads();

        float d0 = 0.f, d1 = 0.f;
        for (int j = s + tid; j < e; j += 128) {
            int src = g_csr[j];
            float4 b0 = g_att0[src]; float2 b1 = g_att1[src];
            d0 += __expf(leaky(b0.x + ed0) - m0);
            d1 += __expf(leaky(b0.z + b1.x + ed1) - m1);
        }
#pragma unroll
        for (int o = 16; o; o >>= 1) {
            d0 += __shfl_xor_sync(0xffffffffu, d0, o);
            d1 += __shfl_xor_sync(0xffffffffu, d1, o);
        }
        if (lane == 0) { w0[warp] = d0; w1[warp] = d1; }
        __syncthreads();
        d0 = w0[0] + w0[1] + w0[2] + w0[3] + 1e-16f;
        d1 = w1[0] + w1[1] + w1[2] + w1[3] + 1e-16f;
        float r0 = 1.0f / d0, r1 = 1.0f / d1;

        for (int base = s; base < e; base += 128) {
            int j = base + tid;
            if (j < e) {
                int src = g_csr[j];
                float4 b0 = g_att0[src]; float2 b1 = g_att1[src];
                s_src[tid] = src;
                s_a0[tid] = __expf(leaky(b0.x + ed0) - m0) * r0;
                s_a1[tid] = __expf(leaky(b0.z + b1.x + ed1) - m1) * r1;
            }
            __syncthreads();
            int cnt = min(128, e - base);
            if (act) {
#pragma unroll 4
                for (int k = 0; k < cnt; k++) {
                    int sk = s_src[k];
                    __half2 hv2 = *(const __half2*)(g_hh + (size_t)sk * 256 + c0);
                    float2 hv = __half22float2(hv2);
                    float aa = head0a ? s_a0[k] : s_a1[k];
                    float ab = head0b ? s_a0[k] : s_a1[k];
                    acc0 += aa * hv.x;
                    acc1 += ab * hv.y;
                }
            }
            __syncthreads();
        }
    }

    if (f32out) {
        if (act) {
            float v0 = fmaxf(acc0 + bias[c0], 0.f);
            float v1 = fmaxf(acc1 + bias[c0 + 1], 0.f);
            of32[(size_t)i * CHN + c0]     = v0;
            of32[(size_t)i * CHN + c0 + 1] = v1;
        }
    } else {
        size_t o = (size_t)i * KP2 + c0;
        if (act) {
            float v0 = fmaxf(acc0 + bias[c0], 0.f);
            float v1 = fmaxf(acc1 + bias[c0 + 1], 0.f);
            *(__half2*)(oh + o) = __floats2half2_rn(v0, v1);
        } else {
            *(__half2*)(oh + o) = __floats2half2_rn(0.f, 0.f);
        }
    }
}

// ---------------- fused pool + 4-layer MLP (one block per graph) ---------------
__global__ __launch_bounds__(256) void pool_mlp_kernel(
    const int* __restrict__ batch, const float* __restrict__ feat,
    const float* __restrict__ lw1, const float* __restrict__ lb1,
    const float* __restrict__ lw2, const float* __restrict__ lb2,
    const float* __restrict__ lw3, const float* __restrict__ lb3,
    const float* __restrict__ lw4, const float* __restrict__ lb4,
    float* __restrict__ out)
{
    int g = blockIdx.x;
    int tid = threadIdx.x;
    __shared__ int ss, se;
    __shared__ float sg[CHN], t1[200], t2[100], t3[100];

    if (tid == 0) {
        int lo = 0, hi = NN;
        while (lo < hi) { int mid = (lo + hi) >> 1; if (batch[mid] < g) lo = mid + 1; else hi = mid; }
        ss = lo;
        lo = 0; hi = NN;
        while (lo < hi) { int mid = (lo + hi) >> 1; if (batch[mid] < g + 1) lo = mid + 1; else hi = mid; }
        se = lo;
    }
    __syncthreads();
    if (tid < CHN) {
        float sum = 0.f;
        for (int i = ss; i < se; i++) sum += feat[(size_t)i * CHN + tid];
        sg[tid] = sum / fmaxf((float)(se - ss), 1.0f);
    }
    __syncthreads();
    if (tid < 200) {
        float s = lb1[tid];
        for (int k = 0; k < 250; k++) s += sg[k] * lw1[k * 200 + tid];
        t1[tid] = fmaxf(s, 0.f);
    }
    __syncthreads();
    if (tid < 100) {
        float s = lb2[tid];
        for (int k = 0; k < 200; k++) s += t1[k] * lw2[k * 100 + tid];
        t2[tid] = fmaxf(s, 0.f);
    }
    __syncthreads();
    if (tid < 100) {
        float s = lb3[tid];
        for (int k = 0; k < 100; k++) s += t2[k] * lw3[k * 100 + tid];
        t3[tid] = fmaxf(s, 0.f);
    }
    __syncthreads();
    if (tid < 29) {
        float s = lb4[tid];
        for (int k = 0; k < 100; k++) s += t3[k] * lw4[k * 29 + tid];
        out[g * 29 + tid] = s;
    }
}

// ---------------- driver --------------------------------------------------------
extern "C" void kernel_launch(void* const* d_in, const int* in_sizes, int n_in,
                              void* d_out, int out_size)
{
    const float* x     = (const float*)d_in[0];
    const int*   ei    = (const int*)d_in[1];
    const int*   batch = (const int*)d_in[2];
    const float* W[4]    = {(const float*)d_in[3],  (const float*)d_in[7],
                            (const float*)d_in[11], (const float*)d_in[15]};
    const float* Asrc[4] = {(const float*)d_in[4],  (const float*)d_in[8],
                            (const float*)d_in[12], (const float*)d_in[16]};
    const float* Adst[4] = {(const float*)d_in[5],  (const float*)d_in[9],
                            (const float*)d_in[13], (const float*)d_in[17]};
    const float* Bb[4]   = {(const float*)d_in[6],  (const float*)d_in[10],
                            (const float*)d_in[14], (const float*)d_in[18]};
    const float* lw1 = (const float*)d_in[19]; const float* lb1 = (const float*)d_in[20];
    const float* lw2 = (const float*)d_in[21]; const float* lb2 = (const float*)d_in[22];
    const float* lw3 = (const float*)d_in[23]; const float* lb3 = (const float*)d_in[24];
    const float* lw4 = (const float*)d_in[25]; const float* lb4 = (const float*)d_in[26];
    float* out = (float*)d_out;

    float *faP;
    __half *hhP, *a1hP, *a2hP, *whP, *wlP;
    cudaGetSymbolAddress((void**)&hhP,  g_hh);
    cudaGetSymbolAddress((void**)&faP,  g_fa);
    cudaGetSymbolAddress((void**)&a1hP, g_a1h);
    cudaGetSymbolAddress((void**)&a2hP, g_a2h);
    cudaGetSymbolAddress((void**)&whP,  g_wh);
    cudaGetSymbolAddress((void**)&wlP,  g_wl);

    cudaFuncSetAttribute(gemm_wmma_kernel,
                         cudaFuncAttributeMaxDynamicSharedMemorySize, GEMM_SMEM);

    init_kernel<<<(NN + 112 * KP2 + 255) / 256, 256>>>();
    count_kernel<<<(ET + 255) / 256, 256>>>(ei);
    scan_kernel<<<1, 1024>>>();
    scatter_kernel<<<(ET + 255) / 256, 256>>>(ei);

    split_a_kernel<<<(MPAD * KP1 + 255) / 256, 256>>>(x);
    int wtotal = NT * KP1 + 3 * NT * KP2;
    split_w_all_kernel<<<(wtotal + 255) / 256, 256>>>(W[0], W[1], W[2], W[3]);

    dim3 ggrid(MPAD / MT2, 2);
    for (int l = 0; l < 4; l++) {
        const __half* Ain = (l == 0) ? a1hP : a2hP;
        int Kpad = (l == 0) ? KP1 : KP2;
        size_t woff = (l == 0) ? 0 : (size_t)WOFF1 + (size_t)(l - 1) * NT * KP2;
        gemm_wmma_kernel<<<ggrid, 256, GEMM_SMEM>>>(
            Ain, whP + woff, wlP + woff, Kpad, Asrc[l], Adst[l], hhP);
        agg_kernel<<<NN, 128>>>(Bb[l], a2hP, faP, (l == 3) ? 1 : 0);
    }

    pool_mlp_kernel<<<GG, 256>>>(batch, faP, lw1, lb1, lw2, lb2, lw3, lb3, lw4, lb4, out);
}

// round 12
// speedup vs baseline: 1.8382x; 1.1430x over previous
#include <cuda_runtime.h>
#include <cuda_fp16.h>
#include <mma.h>
#include <cstdint>

using namespace nvcuda;

#define NN    10000
#define EE    320000
#define ET    330000
#define GG    100
#define CHN   250
#define HOUT  125
#define SLOPE 0.2f

#define MT2   64        // GEMM M tile
#define NT    256
#define MPAD  10112     // 158 * 64
#define KP1   384
#define KP2   256

// ---------------- scratch ------------------------------------------------------
__device__ __half g_hh[MPAD * 256];          // GEMM output fp16 (gather source)
__device__ __half g_a2h[MPAD * 256];         // layers 2-4 GEMM A input fp16 (agg-written)
__device__ float  g_fa[NN * CHN];            // layer-4 output fp32 (pool source)
__device__ float4 g_att0[NN];
__device__ float2 g_att1[NN];
__device__ int    g_cnt[NN];
__device__ int    g_off[NN + 1];
__device__ int    g_pos[NN];
__device__ int    g_csr[ET];
__device__ __align__(256) __half g_a1h[MPAD * KP1];   // layer1 A fp16
#define WOFF1 (NT * KP1)
__device__ __align__(256) __half g_wh[NT * KP1 + 3 * NT * KP2];

// ---------------- helpers ------------------------------------------------------
__device__ __forceinline__ uint32_t smem_u32(const void* p) {
    uint32_t a;
    asm("{ .reg .u64 t; cvta.to.shared.u64 t, %1; cvt.u32.u64 %0, t; }" : "=r"(a) : "l"(p));
    return a;
}
__device__ __forceinline__ void cp_async16(uint32_t dst, const void* src) {
    asm volatile("cp.async.cg.shared.global [%0], [%1], 16;" :: "r"(dst), "l"(src));
}
__device__ __forceinline__ void cp_commit() { asm volatile("cp.async.commit_group;" ::: "memory"); }
__device__ __forceinline__ void cp_wait2()  { asm volatile("cp.async.wait_group 2;" ::: "memory"); }
__device__ __forceinline__ float leaky(float x) { return x > 0.f ? x : SLOPE * x; }

// ---------------- init ----------------------------------------------------------
__global__ void init_kernel() {
    int i = blockIdx.x * blockDim.x + threadIdx.x;
    if (i < NN) g_cnt[i] = 0;
    int p = i - NN;
    if (p >= 0 && p < 112 * KP2) {
        g_a2h[10000 * KP2 + p] = __float2half(0.f);
    }
}
__global__ void count_kernel(const int* __restrict__ ei) {
    int i = blockIdx.x * blockDim.x + threadIdx.x;
    if (i >= ET) return;
    int dst = (i < EE) ? ei[EE + i] : (i - EE);
    atomicAdd(&g_cnt[dst], 1);
}
__global__ void scan_kernel() {
    __shared__ int sp[1024];
    int t = threadIdx.x;
    int base = t * 10;
    int loc[10];
    int sum = 0;
#pragma unroll
    for (int i = 0; i < 10; i++) {
        int idx = base + i;
        int v = (idx < NN) ? g_cnt[idx] : 0;
        loc[i] = sum; sum += v;
    }
    sp[t] = sum;
    __syncthreads();
    for (int off = 1; off < 1024; off <<= 1) {
        int v = (t >= off) ? sp[t - off] : 0;
        __syncthreads();
        sp[t] += v;
        __syncthreads();
    }
    int pre = sp[t] - sum;
#pragma unroll
    for (int i = 0; i < 10; i++) {
        int idx = base + i;
        if (idx < NN) { int o = pre + loc[i]; g_off[idx] = o; g_pos[idx] = o; }
    }
    if (t == 1023) g_off[NN] = sp[1023];
}
__global__ void scatter_kernel(const int* __restrict__ ei) {
    int i = blockIdx.x * blockDim.x + threadIdx.x;
    if (i >= ET) return;
    int src, dst;
    if (i < EE) { src = ei[i]; dst = ei[EE + i]; }
    else        { src = i - EE; dst = i - EE; }
    int p = atomicAdd(&g_pos[dst], 1);
    g_csr[p] = src;
}

// ---------------- splits -------------------------------------------------------
__global__ void split_a_kernel(const float* __restrict__ in) {
    int idx = blockIdx.x * blockDim.x + threadIdx.x;
    if (idx >= MPAD * KP1) return;
    int r = idx / KP1, k = idx - r * KP1;
    float v = (r < NN && k < 336) ? in[(size_t)r * 336 + k] : 0.f;
    g_a1h[idx] = __float2half(v);
}
__global__ void split_w_all_kernel(const float* __restrict__ W1, const float* __restrict__ W2,
                                   const float* __restrict__ W3, const float* __restrict__ W4)
{
    int idx = blockIdx.x * blockDim.x + threadIdx.x;
    int total = NT * KP1 + 3 * NT * KP2;
    if (idx >= total) return;
    const float* W; int K, Kpad, rem;
    if (idx < NT * KP1) { W = W1; K = 336; Kpad = KP1; rem = idx; }
    else {
        int idx2 = idx - NT * KP1;
        int l = idx2 / (NT * KP2);
        rem = idx2 - l * (NT * KP2);
        W = (l == 0) ? W2 : (l == 1) ? W3 : W4;
        K = 250; Kpad = KP2;
    }
    int n = rem / Kpad, k = rem - n * Kpad;
    float v = (n < CHN && k < K) ? W[(size_t)k * CHN + n] : 0.f;
    g_wh[idx] = __float2half(v);
}

// ---------------- WMMA fp16 GEMM: 64x128 tile, K' = Kpad ------------------------
#define ALD   40
#define BLD   40
#define A_ELE (64 * ALD)
#define B_ELE (128 * BLD)
#define STG_ELE (A_ELE + B_ELE)   // 7680 halves = 15360 B
#define CLD   136
#define GEMM_SMEM (4 * STG_ELE * 2)

__global__ __launch_bounds__(256) void gemm_wmma_kernel(
    const __half* __restrict__ Ain, const __half* __restrict__ Bin,
    int Kpad,
    const float* __restrict__ asrc, const float* __restrict__ adst,
    __half* __restrict__ hout)
{
    extern __shared__ char smem[];
    float* Cs = (float*)smem;
    __shared__ float s_as[128], s_ad[128];

    int tid = threadIdx.x;
    int wid = tid >> 5;
    int wm = wid >> 2, wn = wid & 3;
    int m0 = blockIdx.x * MT2;
    int by = blockIdx.y;
    int n0 = by * 128;

    if (tid < 128) {
        int col = n0 + tid;
        s_as[tid] = (col < CHN) ? asrc[col] : 0.f;
        s_ad[tid] = (col < CHN) ? adst[col] : 0.f;
    }

    uint32_t sbase = smem_u32(smem);
    int niter = Kpad >> 5;           // 12 (l1) / 8 (l2-4)

    auto load_stage = [&](int st, int kb) {
        int kk = kb << 5;
        uint32_t stb = sbase + st * STG_ELE * 2;
        {
            int rowa = tid >> 2, grpa = tid & 3;
            cp_async16(stb + (rowa * ALD + grpa * 8) * 2,
                       Ain + (size_t)(m0 + rowa) * Kpad + kk + grpa * 8);
        }
#pragma unroll
        for (int i = 0; i < 2; i++) {
            int c = tid + i * 256;
            int rowb = c >> 2, grpb = c & 3;
            cp_async16(stb + (A_ELE + rowb * BLD + grpb * 8) * 2,
                       Bin + (size_t)(n0 + rowb) * Kpad + kk + grpb * 8);
        }
        cp_commit();
    };

    wmma::fragment<wmma::accumulator, 16, 16, 16, float> c[2][2];
#pragma unroll
    for (int i = 0; i < 2; i++)
#pragma unroll
        for (int j = 0; j < 2; j++) wmma::fill_fragment(c[i][j], 0.f);

    load_stage(0, 0);
    load_stage(1, 1);
    load_stage(2, 2);

    for (int kb = 0; kb < niter; kb++) {
        cp_wait2();
        __syncthreads();
        if (kb + 3 < niter) load_stage((kb + 3) & 3, kb + 3);
        else                cp_commit();

        const __half* stg = (const __half*)(smem + (size_t)(kb & 3) * STG_ELE * 2);
        const __half* at = stg + wm * 32 * ALD;
        const __half* bt = stg + A_ELE + wn * 32 * BLD;
#pragma unroll
        for (int ks = 0; ks < 2; ks++) {
            wmma::fragment<wmma::matrix_a, 16, 16, 16, __half, wmma::row_major> a0, a1;
            wmma::load_matrix_sync(a0, at + ks * 16, ALD);
            wmma::load_matrix_sync(a1, at + 16 * ALD + ks * 16, ALD);
            wmma::fragment<wmma::matrix_b, 16, 16, 16, __half, wmma::col_major> b0, b1;
            wmma::load_matrix_sync(b0, bt + ks * 16, BLD);
            wmma::load_matrix_sync(b1, bt + 16 * BLD + ks * 16, BLD);
            wmma::mma_sync(c[0][0], a0, b0, c[0][0]);
            wmma::mma_sync(c[0][1], a0, b1, c[0][1]);
            wmma::mma_sync(c[1][0], a1, b0, c[1][0]);
            wmma::mma_sync(c[1][1], a1, b1, c[1][1]);
        }
    }
    __syncthreads();

#pragma unroll
    for (int i = 0; i < 2; i++)
#pragma unroll
        for (int j = 0; j < 2; j++)
            wmma::store_matrix_sync(Cs + (wm * 32 + i * 16) * CLD + wn * 32 + j * 16,
                                    c[i][j], CLD, wmma::mem_row_major);
    __syncthreads();

    // coalesced fp16 store (stride 256)
#pragma unroll
    for (int it = 0; it < 16; it++) {
        int idx = it * 256 + tid;
        int r = idx >> 6, c2 = idx & 63;
        int grow = m0 + r, gcol = n0 + 2 * c2;
        if (grow < NN && gcol < CHN) {
            float v0 = Cs[r * CLD + 2 * c2];
            float v1 = Cs[r * CLD + 2 * c2 + 1];
            *(__half2*)(hout + (size_t)grow * 256 + gcol) = __floats2half2_rn(v0, v1);
        }
    }

    // fused attention dots
    if (tid < 128) {
        int r = tid >> 1;
        int half = tid & 1;
        int ccb = half * 64;
        float s0 = 0.f, d0 = 0.f, s1 = 0.f, d1 = 0.f;
#pragma unroll 8
        for (int q = 0; q < 64; q++) {
            int cc = ccb + q;
            float v = Cs[r * CLD + cc];
            float a = s_as[cc], bvd = s_ad[cc];
            if (n0 + cc < HOUT) { s0 += v * a; d0 += v * bvd; }
            else                { s1 += v * a; d1 += v * bvd; }
        }
        s0 += __shfl_xor_sync(0xffffffffu, s0, 1);
        d0 += __shfl_xor_sync(0xffffffffu, d0, 1);
        s1 += __shfl_xor_sync(0xffffffffu, s1, 1);
        d1 += __shfl_xor_sync(0xffffffffu, d1, 1);
        int grow = m0 + r;
        if (half == 0 && grow < NN) {
            if (by == 0) g_att0[grow] = make_float4(s0, d0, s1, d1);
            else         g_att1[grow] = make_float2(s1, d1);
        }
    }
}

// ---------------- aggregation: single-pass softmax + fp16 gather ----------------
__global__ __launch_bounds__(128) void agg_kernel(const float* __restrict__ bias,
                                                  __half* __restrict__ oh,
                                                  float* __restrict__ of32,
                                                  int f32out)
{
    int i = blockIdx.x;
    int tid = threadIdx.x;
    int lane = tid & 31, warp = tid >> 5;

    __shared__ float w0[4], w1[4];
    __shared__ int   s_src[128];
    __shared__ float s_a0[128], s_a1[128];

    int s = g_off[i], e = g_off[i + 1];
    int d = e - s;
    float4 a0i = g_att0[i];
    float2 a1i = g_att1[i];
    float ed0 = a0i.y, ed1 = a0i.w + a1i.y;

    float acc0 = 0.f, acc1 = 0.f;
    int c0 = 2 * tid;
    bool act = (tid < HOUT);
    bool head0a = (c0 < HOUT);
    bool head0b = (c0 + 1 < HOUT);

    if (d <= 128) {
        bool valid = tid < d;
        int src = 0;
        float l0 = -1e30f, l1 = -1e30f;
        if (valid) {
            src = g_csr[s + tid];
            float4 b0 = g_att0[src]; float2 b1 = g_att1[src];
            l0 = leaky(b0.x + ed0);
            l1 = leaky(b0.z + b1.x + ed1);
        }
        float m0 = l0, m1 = l1;
#pragma unroll
        for (int o = 16; o; o >>= 1) {
            m0 = fmaxf(m0, __shfl_xor_sync(0xffffffffu, m0, o));
            m1 = fmaxf(m1, __shfl_xor_sync(0xffffffffu, m1, o));
        }
        if (lane == 0) { w0[warp] = m0; w1[warp] = m1; }
        __syncthreads();
        m0 = fmaxf(fmaxf(w0[0], w0[1]), fmaxf(w0[2], w0[3]));
        m1 = fmaxf(fmaxf(w1[0], w1[1]), fmaxf(w1[2], w1[3]));
        __syncthreads();

        float p0 = valid ? __expf(l0 - m0) : 0.f;
        float p1 = valid ? __expf(l1 - m1) : 0.f;
        float d0 = p0, d1 = p1;
#pragma unroll
        for (int o = 16; o; o >>= 1) {
            d0 += __shfl_xor_sync(0xffffffffu, d0, o);
            d1 += __shfl_xor_sync(0xffffffffu, d1, o);
        }
        if (lane == 0) { w0[warp] = d0; w1[warp] = d1; }
        __syncthreads();
        d0 = w0[0] + w0[1] + w0[2] + w0[3] + 1e-16f;
        d1 = w1[0] + w1[1] + w1[2] + w1[3] + 1e-16f;
        float r0 = 1.0f / d0, r1 = 1.0f / d1;

        s_src[tid] = src;
        s_a0[tid] = p0 * r0;
        s_a1[tid] = p1 * r1;
        __syncthreads();

        if (act) {
#pragma unroll 4
            for (int k = 0; k < d; k++) {
                int sk = s_src[k];
                __half2 hv2 = *(const __half2*)(g_hh + (size_t)sk * 256 + c0);
                float2 hv = __half22float2(hv2);
                float aa = head0a ? s_a0[k] : s_a1[k];
                float ab = head0b ? s_a0[k] : s_a1[k];
                acc0 += aa * hv.x;
                acc1 += ab * hv.y;
            }
        }
    } else {
        float m0 = -1e30f, m1 = -1e30f;
        for (int j = s + tid; j < e; j += 128) {
            int src = g_csr[j];
            float4 b0 = g_att0[src]; float2 b1 = g_att1[src];
            m0 = fmaxf(m0, leaky(b0.x + ed0));
            m1 = fmaxf(m1, leaky(b0.z + b1.x + ed1));
        }
#pragma unroll
        for (int o = 16; o; o >>= 1) {
            m0 = fmaxf(m0, __shfl_xor_sync(0xffffffffu, m0, o));
            m1 = fmaxf(m1, __shfl_xor_sync(0xffffffffu, m1, o));
        }
        if (lane == 0) { w0[warp] = m0; w1[warp] = m1; }
        __syncthreads();
        m0 = fmaxf(fmaxf(w0[0], w0[1]), fmaxf(w0[2], w0[3]));
        m1 = fmaxf(fmaxf(w1[0], w1[1]), fmaxf(w1[2], w1[3]));
        __syncthreads();

        float d0 = 0.f, d1 = 0.f;
        for (int j = s + tid; j < e; j += 128) {
            int src = g_csr[j];
            float4 b0 = g_att0[src]; float2 b1 = g_att1[src];
            d0 += __expf(leaky(b0.x + ed0) - m0);
            d1 += __expf(leaky(b0.z + b1.x + ed1) - m1);
        }
#pragma unroll
        for (int o = 16; o; o >>= 1) {
            d0 += __shfl_xor_sync(0xffffffffu, d0, o);
            d1 += __shfl_xor_sync(0xffffffffu, d1, o);
        }
        if (lane == 0) { w0[warp] = d0; w1[warp] = d1; }
        __syncthreads();
        d0 = w0[0] + w0[1] + w0[2] + w0[3] + 1e-16f;
        d1 = w1[0] + w1[1] + w1[2] + w1[3] + 1e-16f;
        float r0 = 1.0f / d0, r1 = 1.0f / d1;

        for (int base = s; base < e; base += 128) {
            int j = base + tid;
            if (j < e) {
                int src = g_csr[j];
                float4 b0 = g_att0[src]; float2 b1 = g_att1[src];
                s_src[tid] = src;
                s_a0[tid] = __expf(leaky(b0.x + ed0) - m0) * r0;
                s_a1[tid] = __expf(leaky(b0.z + b1.x + ed1) - m1) * r1;
            }
            __syncthreads();
            int cnt = min(128, e - base);
            if (act) {
#pragma unroll 4
                for (int k = 0; k < cnt; k++) {
                    int sk = s_src[k];
                    __half2 hv2 = *(const __half2*)(g_hh + (size_t)sk * 256 + c0);
                    float2 hv = __half22float2(hv2);
                    float aa = head0a ? s_a0[k] : s_a1[k];
                    float ab = head0b ? s_a0[k] : s_a1[k];
                    acc0 += aa * hv.x;
                    acc1 += ab * hv.y;
                }
            }
            __syncthreads();
        }
    }

    if (f32out) {
        if (act) {
            float v0 = fmaxf(acc0 + bias[c0], 0.f);
            float v1 = fmaxf(acc1 + bias[c0 + 1], 0.f);
            of32[(size_t)i * CHN + c0]     = v0;
            of32[(size_t)i * CHN + c0 + 1] = v1;
        }
    } else {
        size_t o = (size_t)i * KP2 + c0;
        if (act) {
            float v0 = fmaxf(acc0 + bias[c0], 0.f);
            float v1 = fmaxf(acc1 + bias[c0 + 1], 0.f);
            *(__half2*)(oh + o) = __floats2half2_rn(v0, v1);
        } else {
            *(__half2*)(oh + o) = __floats2half2_rn(0.f, 0.f);
        }
    }
}

// ---------------- fused pool + 4-layer MLP (one block per graph) ---------------
__global__ __launch_bounds__(256) void pool_mlp_kernel(
    const int* __restrict__ batch, const float* __restrict__ feat,
    const float* __restrict__ lw1, const float* __restrict__ lb1,
    const float* __restrict__ lw2, const float* __restrict__ lb2,
    const float* __restrict__ lw3, const float* __restrict__ lb3,
    const float* __restrict__ lw4, const float* __restrict__ lb4,
    float* __restrict__ out)
{
    int g = blockIdx.x;
    int tid = threadIdx.x;
    __shared__ int ss, se;
    __shared__ float sg[CHN], t1[200], t2[100], t3[100];

    if (tid == 0) {
        int lo = 0, hi = NN;
        while (lo < hi) { int mid = (lo + hi) >> 1; if (batch[mid] < g) lo = mid + 1; else hi = mid; }
        ss = lo;
        lo = 0; hi = NN;
        while (lo < hi) { int mid = (lo + hi) >> 1; if (batch[mid] < g + 1) lo = mid + 1; else hi = mid; }
        se = lo;
    }
    __syncthreads();
    if (tid < CHN) {
        float sum = 0.f;
        for (int i = ss; i < se; i++) sum += feat[(size_t)i * CHN + tid];
        sg[tid] = sum / fmaxf((float)(se - ss), 1.0f);
    }
    __syncthreads();
    if (tid < 200) {
        float s = lb1[tid];
        for (int k = 0; k < 250; k++) s += sg[k] * lw1[k * 200 + tid];
        t1[tid] = fmaxf(s, 0.f);
    }
    __syncthreads();
    if (tid < 100) {
        float s = lb2[tid];
        for (int k = 0; k < 200; k++) s += t1[k] * lw2[k * 100 + tid];
        t2[tid] = fmaxf(s, 0.f);
    }
    __syncthreads();
    if (tid < 100) {
        float s = lb3[tid];
        for (int k = 0; k < 100; k++) s += t2[k] * lw3[k * 100 + tid];
        t3[tid] = fmaxf(s, 0.f);
    }
    __syncthreads();
    if (tid < 29) {
        float s = lb4[tid];
        for (int k = 0; k < 100; k++) s += t3[k] * lw4[k * 29 + tid];
        out[g * 29 + tid] = s;
    }
}

// ---------------- driver --------------------------------------------------------
extern "C" void kernel_launch(void* const* d_in, const int* in_sizes, int n_in,
                              void* d_out, int out_size)
{
    const float* x     = (const float*)d_in[0];
    const int*   ei    = (const int*)d_in[1];
    const int*   batch = (const int*)d_in[2];
    const float* W[4]    = {(const float*)d_in[3],  (const float*)d_in[7],
                            (const float*)d_in[11], (const float*)d_in[15]};
    const float* Asrc[4] = {(const float*)d_in[4],  (const float*)d_in[8],
                            (const float*)d_in[12], (const float*)d_in[16]};
    const float* Adst[4] = {(const float*)d_in[5],  (const float*)d_in[9],
                            (const float*)d_in[13], (const float*)d_in[17]};
    const float* Bb[4]   = {(const float*)d_in[6],  (const float*)d_in[10],
                            (const float*)d_in[14], (const float*)d_in[18]};
    const float* lw1 = (const float*)d_in[19]; const float* lb1 = (const float*)d_in[20];
    const float* lw2 = (const float*)d_in[21]; const float* lb2 = (const float*)d_in[22];
    const float* lw3 = (const float*)d_in[23]; const float* lb3 = (const float*)d_in[24];
    const float* lw4 = (const float*)d_in[25]; const float* lb4 = (const float*)d_in[26];
    float* out = (float*)d_out;

    float *faP;
    __half *hhP, *a1hP, *a2hP, *whP;
    cudaGetSymbolAddress((void**)&hhP,  g_hh);
    cudaGetSymbolAddress((void**)&faP,  g_fa);
    cudaGetSymbolAddress((void**)&a1hP, g_a1h);
    cudaGetSymbolAddress((void**)&a2hP, g_a2h);
    cudaGetSymbolAddress((void**)&whP,  g_wh);

    cudaFuncSetAttribute(gemm_wmma_kernel,
                         cudaFuncAttributeMaxDynamicSharedMemorySize, GEMM_SMEM);

    init_kernel<<<(NN + 112 * KP2 + 255) / 256, 256>>>();
    count_kernel<<<(ET + 255) / 256, 256>>>(ei);
    scan_kernel<<<1, 1024>>>();
    scatter_kernel<<<(ET + 255) / 256, 256>>>(ei);

    split_a_kernel<<<(MPAD * KP1 + 255) / 256, 256>>>(x);
    int wtotal = NT * KP1 + 3 * NT * KP2;
    split_w_all_kernel<<<(wtotal + 255) / 256, 256>>>(W[0], W[1], W[2], W[3]);

    dim3 ggrid(MPAD / MT2, 2);
    for (int l = 0; l < 4; l++) {
        const __half* Ain = (l == 0) ? a1hP : a2hP;
        int Kpad = (l == 0) ? KP1 : KP2;
        size_t woff = (l == 0) ? 0 : (size_t)WOFF1 + (size_t)(l - 1) * NT * KP2;
        gemm_wmma_kernel<<<ggrid, 256, GEMM_SMEM>>>(
            Ain, whP + woff, Kpad, Asrc[l], Adst[l], hhP);
        agg_kernel<<<NN, 128>>>(Bb[l], a2hP, faP, (l == 3) ? 1 : 0);
    }

    pool_mlp_kernel<<<GG, 256>>>(batch, faP, lw1, lb1, lw2, lb2, lw3, lb3, lw4, lb4, out);
}